// round 2
// baseline (speedup 1.0000x reference)
#include <cuda_runtime.h>
#include <math.h>

#define BATCH 16
#define CCH   256
#define HW    4096
#define OQ    384      // 3*hidden
#define HID   128
#define NGRP  32
#define CPG   8
#define EPS   1e-5f

// -------- scratch (static device arrays; no runtime allocation) --------
__device__ float g_scale[BATCH*CCH];     // a[b,c] = gn_w * rsqrt(var+eps)
__device__ float g_shift[BATCH*CCH];     // s[b,c] = gn_b - mean*a
__device__ float g_bq[BATCH*OQ];         // folded qkv bias
__device__ float g_qkv[(size_t)BATCH*OQ*HW];   // q rows 0..127, k 128..255, v 256..383
__device__ float g_rmax[BATCH*HID];
__device__ float g_rsum[BATCH*HID];
__device__ float g_ctx[BATCH*4*32*32];
__device__ float g_M[BATCH*CCH*HID];     // folded out_w @ ctx

// -------- 1) GroupNorm stats -> per-channel affine --------
__global__ void k_gnstats(const float* __restrict__ x,
                          const float* __restrict__ gn_w,
                          const float* __restrict__ gn_b) {
    int g = blockIdx.x, b = blockIdx.y;
    const float4* p4 = (const float4*)(x + ((size_t)b*CCH + g*CPG)*HW);
    const int n4 = CPG*HW/4;  // 8192 float4s, contiguous
    float s = 0.f, s2 = 0.f;
    for (int i = threadIdx.x; i < n4; i += blockDim.x) {
        float4 v = p4[i];
        s  += v.x + v.y + v.z + v.w;
        s2 += v.x*v.x + v.y*v.y + v.z*v.z + v.w*v.w;
    }
    __shared__ float ss[256], ss2[256];
    ss[threadIdx.x] = s; ss2[threadIdx.x] = s2;
    __syncthreads();
    for (int o = 128; o > 0; o >>= 1) {
        if (threadIdx.x < o) { ss[threadIdx.x] += ss[threadIdx.x+o]; ss2[threadIdx.x] += ss2[threadIdx.x+o]; }
        __syncthreads();
    }
    if (threadIdx.x < CPG) {
        const float inv = 1.0f / (float)(CPG*HW);
        float mean = ss[0] * inv;
        float var  = ss2[0] * inv - mean*mean;
        float r    = rsqrtf(var + EPS);
        int c = g*CPG + threadIdx.x;
        float a = gn_w[c] * r;
        g_scale[b*CCH + c] = a;
        g_shift[b*CCH + c] = gn_b[c] - mean*a;
    }
}

// -------- 2) fold qkv bias: b'[b,o] = qkv_b[o] + sum_c qkv_w[o,c]*shift[b,c] --------
__global__ void k_biasfold(const float* __restrict__ qkv_w,
                           const float* __restrict__ qkv_b) {
    int b = blockIdx.x;
    __shared__ float sh[CCH];
    for (int i = threadIdx.x; i < CCH; i += blockDim.x) sh[i] = g_shift[b*CCH + i];
    __syncthreads();
    for (int o = threadIdx.x; o < OQ; o += blockDim.x) {
        const float* w = qkv_w + (size_t)o*CCH;
        float acc = 0.f;
        #pragma unroll 8
        for (int c = 0; c < CCH; c++) acc += w[c]*sh[c];
        g_bq[b*OQ + o] = qkv_b[o] + acc;
    }
}

// -------- batched SGEMM: C[b] (M x 4096) = A[b] (M x K) * B[b] (K x 4096) + bias --------
// optional per-column (K-dim) scale applied to A on load (GroupNorm fold)
template<bool SCALE>
__global__ __launch_bounds__(256)
void k_sgemm(const float* __restrict__ A, long strideA,
             const float* __restrict__ Bm, long strideB,
             float* __restrict__ Cm, long strideC,
             const float* __restrict__ bias, long strideBias,
             const float* __restrict__ cscale,
             int M, int K) {
    int b = blockIdx.z;
    const float* Ab = A + (size_t)b*strideA;
    const float* Bb = Bm + (size_t)b*strideB;
    float* Cb = Cm + (size_t)b*strideC;
    const float* biasb = bias + (size_t)b*strideBias;
    const float* scb = SCALE ? (cscale + (size_t)b*K) : nullptr;

    const int m0 = blockIdx.y * 128;
    const int n0 = blockIdx.x * 128;
    const int tid = threadIdx.x;
    const int tx = tid & 15, ty = tid >> 4;

    __shared__ float As[8][128];
    __shared__ float Bs[8][128];

    float acc[2][2][4][4];
    #pragma unroll
    for (int a = 0; a < 2; a++)
    #pragma unroll
    for (int c = 0; c < 2; c++)
    #pragma unroll
    for (int i = 0; i < 4; i++)
    #pragma unroll
    for (int j = 0; j < 4; j++) acc[a][c][i][j] = 0.f;

    // load indices
    const int am = tid >> 1, akk = (tid & 1) * 4;
    const int bkk = tid >> 5, bn = (tid & 31) * 4;

    for (int k0 = 0; k0 < K; k0 += 8) {
        {
            float4 a = *(const float4*)&Ab[(size_t)(m0+am)*K + k0 + akk];
            if (SCALE) {
                a.x *= scb[k0+akk]; a.y *= scb[k0+akk+1];
                a.z *= scb[k0+akk+2]; a.w *= scb[k0+akk+3];
            }
            As[akk  ][am] = a.x; As[akk+1][am] = a.y;
            As[akk+2][am] = a.z; As[akk+3][am] = a.w;
        }
        *(float4*)&Bs[bkk][bn] = *(const float4*)&Bb[(size_t)(k0+bkk)*HW + n0 + bn];
        __syncthreads();
        #pragma unroll
        for (int kk = 0; kk < 8; kk++) {
            float4 a0 = *(const float4*)&As[kk][ty*4];
            float4 a1 = *(const float4*)&As[kk][64 + ty*4];
            float4 b0 = *(const float4*)&Bs[kk][tx*4];
            float4 b1 = *(const float4*)&Bs[kk][64 + tx*4];
            float av[2][4] = {{a0.x,a0.y,a0.z,a0.w},{a1.x,a1.y,a1.z,a1.w}};
            float bv[2][4] = {{b0.x,b0.y,b0.z,b0.w},{b1.x,b1.y,b1.z,b1.w}};
            #pragma unroll
            for (int im = 0; im < 2; im++)
            #pragma unroll
            for (int in = 0; in < 2; in++)
            #pragma unroll
            for (int i = 0; i < 4; i++)
            #pragma unroll
            for (int j = 0; j < 4; j++)
                acc[im][in][i][j] += av[im][i] * bv[in][j];
        }
        __syncthreads();
    }

    #pragma unroll
    for (int im = 0; im < 2; im++)
    #pragma unroll
    for (int i = 0; i < 4; i++) {
        int m = m0 + im*64 + ty*4 + i;
        float bi = biasb[m];
        #pragma unroll
        for (int in = 0; in < 2; in++) {
            float4 r;
            r.x = acc[im][in][i][0] + bi;
            r.y = acc[im][in][i][1] + bi;
            r.z = acc[im][in][i][2] + bi;
            r.w = acc[im][in][i][3] + bi;
            *(float4*)&Cb[(size_t)m*HW + n0 + in*64 + tx*4] = r;
        }
    }
}

// -------- 4a) row max + sumexp over spatial for k rows --------
__global__ void k_rowstats() {
    int r = blockIdx.x, b = blockIdx.y;
    const float* row = g_qkv + ((size_t)(b*OQ) + HID + r)*HW;
    const int tid = threadIdx.x;
    __shared__ float sm[256];
    float mx = -INFINITY;
    for (int i = tid; i < HW; i += 256) mx = fmaxf(mx, row[i]);
    sm[tid] = mx; __syncthreads();
    for (int o = 128; o > 0; o >>= 1) {
        if (tid < o) sm[tid] = fmaxf(sm[tid], sm[tid+o]);
        __syncthreads();
    }
    float Mv = sm[0];
    __syncthreads();
    float s = 0.f;
    for (int i = tid; i < HW; i += 256) s += expf(row[i] - Mv);
    sm[tid] = s; __syncthreads();
    for (int o = 128; o > 0; o >>= 1) {
        if (tid < o) sm[tid] += sm[tid+o];
        __syncthreads();
    }
    if (tid == 0) { g_rmax[b*HID + r] = Mv; g_rsum[b*HID + r] = sm[0]; }
}

// -------- 4b) context[b,h,d,e] = sum_n softmax(k)[d,n]*v[e,n] --------
__global__ __launch_bounds__(1024)
void k_context() {
    int h = blockIdx.x, b = blockIdx.y;
    const int tid = threadIdx.x;
    const int d = tid >> 5, e = tid & 31;
    __shared__ float ek[32][128];
    __shared__ float vt[32][129];   // padded for conflict-free lane-strided reads
    const float* kbase = g_qkv + ((size_t)(b*OQ) + HID   + h*32)*HW;
    const float* vbase = g_qkv + ((size_t)(b*OQ) + 2*HID + h*32)*HW;
    const float* rmax  = g_rmax + b*HID + h*32;
    float acc = 0.f;
    for (int n0 = 0; n0 < HW; n0 += 128) {
        #pragma unroll
        for (int i = tid; i < 4096; i += 1024) {
            int r = i >> 7, cc = i & 127;
            ek[r][cc] = expf(kbase[(size_t)r*HW + n0 + cc] - rmax[r]);
            vt[r][cc] = vbase[(size_t)r*HW + n0 + cc];
        }
        __syncthreads();
        #pragma unroll 16
        for (int nn = 0; nn < 128; nn++)
            acc += ek[d][nn] * vt[e][nn];
        __syncthreads();
    }
    g_ctx[(((size_t)b*4 + h)*32 + d)*32 + e] = acc / g_rsum[b*HID + h*32 + d];
}

// -------- 5) fold out_w with context: M[b,o,h*32+d] = sum_e out_w[o,h*32+e]*ctx[b,h,d,e] --------
__global__ void k_fold(const float* __restrict__ out_w) {
    int b = blockIdx.x;
    const int tid = threadIdx.x;
    __shared__ float cs[4*32*32];
    for (int i = tid; i < 4096; i += 256) cs[i] = g_ctx[(size_t)b*4096 + i];
    __syncthreads();
    int o = tid;
    const float* w = out_w + (size_t)o*HID;
    for (int h = 0; h < 4; h++) {
        float wr[32];
        #pragma unroll
        for (int e = 0; e < 32; e++) wr[e] = w[h*32 + e];
        for (int d = 0; d < 32; d++) {
            float acc = 0.f;
            #pragma unroll
            for (int e = 0; e < 32; e++) acc += wr[e] * cs[(h*32 + d)*32 + e];
            g_M[((size_t)b*CCH + o)*HID + h*32 + d] = acc;
        }
    }
}

extern "C" void kernel_launch(void* const* d_in, const int* in_sizes, int n_in,
                              void* d_out, int out_size) {
    const float* x     = (const float*)d_in[0];
    const float* gn_w  = (const float*)d_in[1];
    const float* gn_b  = (const float*)d_in[2];
    const float* qkv_w = (const float*)d_in[3];
    const float* qkv_b = (const float*)d_in[4];
    const float* out_w = (const float*)d_in[5];
    const float* out_b = (const float*)d_in[6];
    float* out = (float*)d_out;

    float *p_scale, *p_qkv, *p_M;
    cudaGetSymbolAddress((void**)&p_scale, g_scale);
    cudaGetSymbolAddress((void**)&p_qkv,   g_qkv);
    cudaGetSymbolAddress((void**)&p_M,     g_M);
    float *p_bq;
    cudaGetSymbolAddress((void**)&p_bq,    g_bq);

    // 1) GroupNorm stats
    k_gnstats<<<dim3(NGRP, BATCH), 256>>>(x, gn_w, gn_b);
    // 2) fold qkv bias
    k_biasfold<<<BATCH, 256>>>(qkv_w, qkv_b);
    // 3) QKV GEMM (scaled weights, folded bias): 384x4096x256 x16
    k_sgemm<true><<<dim3(HW/128, OQ/128, BATCH), 256>>>(
        qkv_w, 0L, x, (long)CCH*HW, p_qkv, (long)OQ*HW,
        p_bq, (long)OQ, p_scale, OQ, CCH);
    // 4a) softmax stats on k rows
    k_rowstats<<<dim3(HID, BATCH), 256>>>();
    // 4b) context
    k_context<<<dim3(4, BATCH), 1024>>>();
    // 5) fold out_w with context
    k_fold<<<BATCH, 256>>>(out_w);
    // 6) final GEMM: out = M @ q + out_b : 256x4096x128 x16
    k_sgemm<false><<<dim3(HW/128, CCH/128, BATCH), 256>>>(
        p_M, (long)CCH*HID, p_qkv, (long)OQ*HW, out, (long)CCH*HW,
        out_b, 0L, nullptr, CCH, HID);
}

// round 7
// speedup vs baseline: 1.6144x; 1.6144x over previous
#include <cuda_runtime.h>
#include <math.h>
#include <stdint.h>

#define BATCH 16
#define CCH   256
#define HW    4096
#define OQ    384      // 3*hidden
#define HID   128
#define NGRP  32
#define CPG   8
#define EPS   1e-5f

// -------- scratch (static device arrays; no runtime allocation) --------
__device__ float g_scale[BATCH*CCH];     // a[b,c] = gn_w * rsqrt(var+eps)
__device__ float g_shift[BATCH*CCH];     // s[b,c] = gn_b - mean*a
__device__ float g_bq[BATCH*OQ];         // folded qkv bias
__device__ float g_qkv[(size_t)BATCH*OQ*HW];   // [b][o][n]  q 0..127, k 128..255, v 256..383
__device__ float g_rmax[BATCH*HID];
__device__ float g_rsum[BATCH*HID];
__device__ float g_ctx[BATCH*4*32*32];
__device__ float g_M[BATCH*CCH*HID];     // folded out_w @ ctx

__device__ __forceinline__ uint32_t tf32u(float x) {
    uint32_t u;
    asm("cvt.rna.tf32.f32 %0, %1;" : "=r"(u) : "f"(x));
    return u;
}
__device__ __forceinline__ float tf32f(float x) { return __uint_as_float(tf32u(x)); }

// -------- 1) GroupNorm stats -> per-channel affine --------
__global__ void k_gnstats(const float* __restrict__ x,
                          const float* __restrict__ gn_w,
                          const float* __restrict__ gn_b) {
    int g = blockIdx.x, b = blockIdx.y;
    const float4* p4 = (const float4*)(x + ((size_t)b*CCH + g*CPG)*HW);
    const int n4 = CPG*HW/4;
    float s = 0.f, s2 = 0.f;
    for (int i = threadIdx.x; i < n4; i += blockDim.x) {
        float4 v = p4[i];
        s  += v.x + v.y + v.z + v.w;
        s2 += v.x*v.x + v.y*v.y + v.z*v.z + v.w*v.w;
    }
    __shared__ float ss[256], ss2[256];
    ss[threadIdx.x] = s; ss2[threadIdx.x] = s2;
    __syncthreads();
    for (int o = 128; o > 0; o >>= 1) {
        if (threadIdx.x < o) { ss[threadIdx.x] += ss[threadIdx.x+o]; ss2[threadIdx.x] += ss2[threadIdx.x+o]; }
        __syncthreads();
    }
    if (threadIdx.x < CPG) {
        const float inv = 1.0f / (float)(CPG*HW);
        float mean = ss[0] * inv;
        float var  = ss2[0] * inv - mean*mean;
        float r    = rsqrtf(var + EPS);
        int c = g*CPG + threadIdx.x;
        float a = gn_w[c] * r;
        g_scale[b*CCH + c] = a;
        g_shift[b*CCH + c] = gn_b[c] - mean*a;
    }
}

// -------- 2) fold qkv bias --------
__global__ void k_biasfold(const float* __restrict__ qkv_w,
                           const float* __restrict__ qkv_b) {
    int b = blockIdx.x;
    __shared__ float sh[CCH];
    for (int i = threadIdx.x; i < CCH; i += blockDim.x) sh[i] = g_shift[b*CCH + i];
    __syncthreads();
    for (int o = threadIdx.x; o < OQ; o += blockDim.x) {
        const float* w = qkv_w + (size_t)o*CCH;
        float acc = 0.f;
        #pragma unroll 8
        for (int c = 0; c < CCH; c++) acc += w[c]*sh[c];
        g_bq[b*OQ + o] = qkv_b[o] + acc;
    }
}

// -------- tf32 mma.sync batched GEMM: C[b] (M x 4096) = A[b] (M x K) * B[b] (K x 4096) + bias --------
// CTA tile 128x128, BK=32. 8 warps (2 x 4); warp tile 64(m) x 32(n) = 4x4 m16n8k8 mmas.
// Optional per-K-column scale on A (GroupNorm fold).
template<bool SCALE>
__global__ __launch_bounds__(256)
void k_mma_gemm(const float* __restrict__ A, long strideA,
                const float* __restrict__ Bm, long strideB,
                float* __restrict__ Cm, long strideC,
                const float* __restrict__ bias, long strideBias,
                const float* __restrict__ cscale,
                int K) {
    const int b = blockIdx.z;
    const float* Ab = A + (size_t)b*strideA;
    const float* Bb = Bm + (size_t)b*strideB;
    float* Cb = Cm + (size_t)b*strideC;
    const float* biasb = bias + (size_t)b*strideBias;
    const float* scb = SCALE ? (cscale + (size_t)b*K) : nullptr;

    const int m0 = blockIdx.y * 128;
    const int n0 = blockIdx.x * 128;
    const int tid = threadIdx.x;
    const int lane = tid & 31, warp = tid >> 5;
    const int warpM = warp >> 2;          // 0..1 -> 64 rows each
    const int warpN = warp & 3;           // 0..3 -> 32 cols each
    const int gq = lane >> 2;             // group id 0..7
    const int tq = lane & 3;              // thread-in-group 0..3

    // As[m][36]: bank = (4m + k) % 32 -> conflict-free frag loads
    // Bs[k][136]: bank = (8k + n) % 32 -> conflict-free frag loads
    __shared__ float As[128][36];
    __shared__ float Bs[32][136];

    float acc[4][4][4];
    #pragma unroll
    for (int i = 0; i < 4; i++)
    #pragma unroll
    for (int j = 0; j < 4; j++)
    #pragma unroll
    for (int r = 0; r < 4; r++) acc[i][j][r] = 0.f;

    for (int kc = 0; kc < K; kc += 32) {
        // load A tile 128 x 32 (4 float4 per thread)
        #pragma unroll
        for (int t = 0; t < 4; t++) {
            int i = tid + t*256;
            int m = i >> 3, k4 = (i & 7) << 2;
            float4 v = *(const float4*)&Ab[(size_t)(m0+m)*K + kc + k4];
            if (SCALE) {
                v.x *= scb[kc+k4]; v.y *= scb[kc+k4+1];
                v.z *= scb[kc+k4+2]; v.w *= scb[kc+k4+3];
            }
            v.x = tf32f(v.x); v.y = tf32f(v.y); v.z = tf32f(v.z); v.w = tf32f(v.w);
            *(float4*)&As[m][k4] = v;
        }
        // load B tile 32 x 128
        #pragma unroll
        for (int t = 0; t < 4; t++) {
            int i = tid + t*256;
            int k = i >> 5, n4 = (i & 31) << 2;
            float4 v = *(const float4*)&Bb[(size_t)(kc+k)*HW + n0 + n4];
            v.x = tf32f(v.x); v.y = tf32f(v.y); v.z = tf32f(v.z); v.w = tf32f(v.w);
            *(float4*)&Bs[k][n4] = v;
        }
        __syncthreads();

        #pragma unroll
        for (int ks = 0; ks < 4; ks++) {
            const int kb = (ks << 3) + tq;
            uint32_t af[4][4];
            #pragma unroll
            for (int mt = 0; mt < 4; mt++) {
                int mb = warpM*64 + mt*16 + gq;
                af[mt][0] = __float_as_uint(As[mb  ][kb  ]);
                af[mt][1] = __float_as_uint(As[mb+8][kb  ]);
                af[mt][2] = __float_as_uint(As[mb  ][kb+4]);
                af[mt][3] = __float_as_uint(As[mb+8][kb+4]);
            }
            uint32_t bf[4][2];
            #pragma unroll
            for (int nt = 0; nt < 4; nt++) {
                int nb = warpN*32 + nt*8 + gq;
                bf[nt][0] = __float_as_uint(Bs[kb  ][nb]);
                bf[nt][1] = __float_as_uint(Bs[kb+4][nb]);
            }
            #pragma unroll
            for (int mt = 0; mt < 4; mt++)
            #pragma unroll
            for (int nt = 0; nt < 4; nt++) {
                asm volatile(
                    "mma.sync.aligned.m16n8k8.row.col.f32.tf32.tf32.f32 "
                    "{%0,%1,%2,%3}, {%4,%5,%6,%7}, {%8,%9}, {%0,%1,%2,%3};"
                    : "+f"(acc[mt][nt][0]), "+f"(acc[mt][nt][1]),
                      "+f"(acc[mt][nt][2]), "+f"(acc[mt][nt][3])
                    : "r"(af[mt][0]), "r"(af[mt][1]), "r"(af[mt][2]), "r"(af[mt][3]),
                      "r"(bf[nt][0]), "r"(bf[nt][1]));
            }
        }
        __syncthreads();
    }

    // epilogue: D[row g | g+8][col 2t, 2t+1]
    #pragma unroll
    for (int mt = 0; mt < 4; mt++) {
        int m1 = m0 + warpM*64 + mt*16 + gq;
        float bi1 = biasb[m1], bi2 = biasb[m1+8];
        #pragma unroll
        for (int nt = 0; nt < 4; nt++) {
            int n = n0 + warpN*32 + nt*8 + tq*2;
            float2 v1 = { acc[mt][nt][0] + bi1, acc[mt][nt][1] + bi1 };
            float2 v2 = { acc[mt][nt][2] + bi2, acc[mt][nt][3] + bi2 };
            *(float2*)&Cb[(size_t)m1*HW + n]     = v1;
            *(float2*)&Cb[(size_t)(m1+8)*HW + n] = v2;
        }
    }
}

// -------- 4a) row max + sumexp over spatial for k rows --------
__global__ void k_rowstats() {
    int r = blockIdx.x, b = blockIdx.y;
    const float* row = g_qkv + ((size_t)(b*OQ) + HID + r)*HW;
    const int tid = threadIdx.x;
    __shared__ float sm[256];
    float mx = -INFINITY;
    for (int i = tid; i < HW; i += 256) mx = fmaxf(mx, row[i]);
    sm[tid] = mx; __syncthreads();
    for (int o = 128; o > 0; o >>= 1) {
        if (tid < o) sm[tid] = fmaxf(sm[tid], sm[tid+o]);
        __syncthreads();
    }
    float Mv = sm[0];
    __syncthreads();
    float s = 0.f;
    for (int i = tid; i < HW; i += 256) s += expf(row[i] - Mv);
    sm[tid] = s; __syncthreads();
    for (int o = 128; o > 0; o >>= 1) {
        if (tid < o) sm[tid] += sm[tid+o];
        __syncthreads();
    }
    if (tid == 0) { g_rmax[b*HID + r] = Mv; g_rsum[b*HID + r] = sm[0]; }
}

// -------- 4b) context[b,h,d,e] = sum_n softmax(k)[d,n]*v[e,n] --------
__global__ __launch_bounds__(1024)
void k_context() {
    int h = blockIdx.x, b = blockIdx.y;
    const int tid = threadIdx.x;
    const int d = tid >> 5, e = tid & 31;
    __shared__ float ek[32][128];
    __shared__ float vt[32][129];
    const float* kbase = g_qkv + ((size_t)(b*OQ) + HID   + h*32)*HW;
    const float* vbase = g_qkv + ((size_t)(b*OQ) + 2*HID + h*32)*HW;
    const float* rmax  = g_rmax + b*HID + h*32;
    float acc = 0.f;
    for (int n0 = 0; n0 < HW; n0 += 128) {
        #pragma unroll
        for (int i = tid; i < 4096; i += 1024) {
            int r = i >> 7, cc = i & 127;
            ek[r][cc] = expf(kbase[(size_t)r*HW + n0 + cc] - rmax[r]);
            vt[r][cc] = vbase[(size_t)r*HW + n0 + cc];
        }
        __syncthreads();
        #pragma unroll 16
        for (int nn = 0; nn < 128; nn++)
            acc += ek[d][nn] * vt[e][nn];
        __syncthreads();
    }
    g_ctx[(((size_t)b*4 + h)*32 + d)*32 + e] = acc / g_rsum[b*HID + h*32 + d];
}

// -------- 5) fold out_w with context: M[b,o,:] --------
__global__ void k_fold(const float* __restrict__ out_w) {
    int b = blockIdx.x;
    const int tid = threadIdx.x;
    __shared__ float cs[4*32*32];
    for (int i = tid; i < 4096; i += 256) cs[i] = g_ctx[(size_t)b*4096 + i];
    __syncthreads();
    int o = tid;
    const float* w = out_w + (size_t)o*HID;
    for (int h = 0; h < 4; h++) {
        float wr[32];
        #pragma unroll
        for (int e = 0; e < 32; e++) wr[e] = w[h*32 + e];
        for (int d = 0; d < 32; d++) {
            float acc = 0.f;
            #pragma unroll
            for (int e = 0; e < 32; e++) acc += wr[e] * cs[(h*32 + d)*32 + e];
            g_M[((size_t)b*CCH + o)*HID + h*32 + d] = acc;
        }
    }
}

extern "C" void kernel_launch(void* const* d_in, const int* in_sizes, int n_in,
                              void* d_out, int out_size) {
    const float* x     = (const float*)d_in[0];
    const float* gn_w  = (const float*)d_in[1];
    const float* gn_b  = (const float*)d_in[2];
    const float* qkv_w = (const float*)d_in[3];
    const float* qkv_b = (const float*)d_in[4];
    const float* out_w = (const float*)d_in[5];
    const float* out_b = (const float*)d_in[6];
    float* out = (float*)d_out;

    float *p_scale, *p_qkv, *p_M, *p_bq;
    cudaGetSymbolAddress((void**)&p_scale, g_scale);
    cudaGetSymbolAddress((void**)&p_qkv,   g_qkv);
    cudaGetSymbolAddress((void**)&p_M,     g_M);
    cudaGetSymbolAddress((void**)&p_bq,    g_bq);

    // 1) GroupNorm stats
    k_gnstats<<<dim3(NGRP, BATCH), 256>>>(x, gn_w, gn_b);
    // 2) fold qkv bias
    k_biasfold<<<BATCH, 256>>>(qkv_w, qkv_b);
    // 3) QKV GEMM (tf32 tensor cores): 384x4096x256 x16
    k_mma_gemm<true><<<dim3(HW/128, OQ/128, BATCH), 256>>>(
        qkv_w, 0L, x, (long)CCH*HW, p_qkv, (long)OQ*HW,
        p_bq, (long)OQ, p_scale, CCH);
    // 4a) softmax stats on k rows
    k_rowstats<<<dim3(HID, BATCH), 256>>>();
    // 4b) context
    k_context<<<dim3(4, BATCH), 1024>>>();
    // 5) fold out_w with context
    k_fold<<<BATCH, 256>>>(out_w);
    // 6) final GEMM (tf32 tensor cores): 256x4096x128 x16
    k_mma_gemm<false><<<dim3(HW/128, CCH/128, BATCH), 256>>>(
        p_M, (long)CCH*HID, p_qkv, (long)OQ*HW, out, (long)CCH*HW,
        out_b, 0L, nullptr, HID);
}

// round 11
// speedup vs baseline: 1.7561x; 1.0878x over previous
#include <cuda_runtime.h>
#include <math.h>
#include <stdint.h>

#define BATCH 16
#define CCH   256
#define HW    4096
#define OQ    384      // 3*hidden
#define HID   128
#define NGRP  32
#define CPG   8
#define EPS   1e-5f

// -------- scratch --------
__device__ float g_scale[BATCH*CCH];
__device__ float g_shift[BATCH*CCH];
__device__ float g_bq[BATCH*OQ];
__device__ float g_xr[(size_t)BATCH*CCH*HW];    // tf32-rounded x
__device__ float g_wA[(size_t)BATCH*OQ*CCH];    // tf32(qkv_w * scale)
__device__ float g_qkv[(size_t)BATCH*OQ*HW];    // [b][o][n] q 0..127 (tf32-rounded), k, v
__device__ float g_ctx[BATCH*4*32*32];
__device__ float g_M[BATCH*CCH*HID];            // tf32-rounded

__device__ __forceinline__ float tf32f(float x) {
    uint32_t u;
    asm("cvt.rna.tf32.f32 %0, %1;" : "=r"(u) : "f"(x));
    return __uint_as_float(u);
}
__device__ __forceinline__ uint32_t smem_u32(const void* p) {
    uint32_t a;
    asm("{ .reg .u64 t; cvta.to.shared.u64 t, %1; cvt.u32.u64 %0, t; }" : "=r"(a) : "l"(p));
    return a;
}
__device__ __forceinline__ void cp16(uint32_t saddr, const void* gptr) {
    asm volatile("cp.async.cg.shared.global [%0], [%1], 16;" :: "r"(saddr), "l"(gptr));
}
#define CP_COMMIT() asm volatile("cp.async.commit_group;" ::: "memory")
#define CP_WAIT1()  asm volatile("cp.async.wait_group 1;" ::: "memory")
#define CP_WAIT0()  asm volatile("cp.async.wait_group 0;" ::: "memory")

// -------- 1) GroupNorm stats + fused tf32 rounding of x --------
__global__ void k_gnstats(const float* __restrict__ x,
                          const float* __restrict__ gn_w,
                          const float* __restrict__ gn_b) {
    int g = blockIdx.x, b = blockIdx.y;
    const size_t base4 = ((size_t)b*CCH + g*CPG)*HW / 4;
    const float4* p4 = (const float4*)x + base4;
    float4* r4 = (float4*)g_xr + base4;
    const int n4 = CPG*HW/4;
    float s = 0.f, s2 = 0.f;
    for (int i = threadIdx.x; i < n4; i += blockDim.x) {
        float4 v = p4[i];
        s  += v.x + v.y + v.z + v.w;
        s2 += v.x*v.x + v.y*v.y + v.z*v.z + v.w*v.w;
        float4 r;
        r.x = tf32f(v.x); r.y = tf32f(v.y); r.z = tf32f(v.z); r.w = tf32f(v.w);
        r4[i] = r;
    }
    __shared__ float ss[256], ss2[256];
    ss[threadIdx.x] = s; ss2[threadIdx.x] = s2;
    __syncthreads();
    for (int o = 128; o > 0; o >>= 1) {
        if (threadIdx.x < o) { ss[threadIdx.x] += ss[threadIdx.x+o]; ss2[threadIdx.x] += ss2[threadIdx.x+o]; }
        __syncthreads();
    }
    if (threadIdx.x < CPG) {
        const float inv = 1.0f / (float)(CPG*HW);
        float mean = ss[0] * inv;
        float var  = ss2[0] * inv - mean*mean;
        float r    = rsqrtf(var + EPS);
        int c = g*CPG + threadIdx.x;
        float a = gn_w[c] * r;
        g_scale[b*CCH + c] = a;
        g_shift[b*CCH + c] = gn_b[c] - mean*a;
    }
}

// -------- 2a) fold qkv bias --------
__global__ void k_biasfold(const float* __restrict__ qkv_w,
                           const float* __restrict__ qkv_b) {
    int b = blockIdx.x;
    __shared__ float sh[CCH];
    for (int i = threadIdx.x; i < CCH; i += blockDim.x) sh[i] = g_shift[b*CCH + i];
    __syncthreads();
    for (int o = threadIdx.x; o < OQ; o += blockDim.x) {
        const float* w = qkv_w + (size_t)o*CCH;
        float acc = 0.f;
        #pragma unroll 8
        for (int c = 0; c < CCH; c++) acc += w[c]*sh[c];
        g_bq[b*OQ + o] = qkv_b[o] + acc;
    }
}

// -------- 2b) pre-scale + tf32-round weights: g_wA[b][o][c] = tf32(qkv_w*scale) --------
__global__ void k_prepw(const float* __restrict__ qkv_w) {
    int b = blockIdx.y;
    int idx = (blockIdx.x*256 + threadIdx.x) * 4;     // grid.x = OQ*CCH/1024 = 96
    int c = idx & (CCH-1);
    float4 w = *(const float4*)&qkv_w[idx];
    const float* sc = g_scale + b*CCH + c;
    float4 r;
    r.x = tf32f(w.x * sc[0]); r.y = tf32f(w.y * sc[1]);
    r.z = tf32f(w.z * sc[2]); r.w = tf32f(w.w * sc[3]);
    *(float4*)&g_wA[(size_t)b*OQ*CCH + idx] = r;
}

// -------- tf32 mma.sync GEMM, cp.async double-buffered --------
// C[b](M x 4096) = A[b](M x K, K-major, pre-rounded) * B[b](K x 4096, pre-rounded) + bias
// CTA 128x128, BK=32, 8 warps (2x4), warp tile 64x32 = 4x4 m16n8k8.
#define SZA (128*36*4)
#define SZB (32*136*4)
#define GSMEM (2*SZA + 2*SZB)
template<bool QROUND>
__global__ __launch_bounds__(256)
void k_mma_gemm(const float* __restrict__ A, long strideA,
                const float* __restrict__ Bm, long strideB,
                float* __restrict__ Cm, long strideC,
                const float* __restrict__ bias, long strideBias,
                int K) {
    extern __shared__ char dsm[];
    const uint32_t sb = smem_u32(dsm);
    const int b = blockIdx.z;
    const float* Ab = A + (size_t)b*strideA;
    const float* Bb = Bm + (size_t)b*strideB;
    float* Cb = Cm + (size_t)b*strideC;
    const float* biasb = bias + (size_t)b*strideBias;

    const int m0 = blockIdx.y * 128;
    const int n0 = blockIdx.x * 128;
    const int tid = threadIdx.x;
    const int lane = tid & 31, warp = tid >> 5;
    const int warpM = warp >> 2, warpN = warp & 3;
    const int gq = lane >> 2, tq = lane & 3;

    // per-thread load coords (4 x 16B each for A and B)
    const int am = tid >> 1;                 // pairs: 2 thr/row, 4 rows per t-step? no:
    // A: idx = tid + t*256 -> m = idx>>3 (0..127), k4 = (idx&7)*4
    // B: idx = tid + t*256 -> k = idx>>5 (0..31),  n4 = (idx&31)*4
    (void)am;

    float acc[4][4][4];
    #pragma unroll
    for (int i = 0; i < 4; i++)
    #pragma unroll
    for (int j = 0; j < 4; j++)
    #pragma unroll
    for (int r = 0; r < 4; r++) acc[i][j][r] = 0.f;

    const int NCH = K >> 5;

    auto load_chunk = [&](int ch, int st) {
        const int kc = ch << 5;
        const uint32_t aBase = sb + st*SZA;
        const uint32_t bBase = sb + 2*SZA + st*SZB;
        #pragma unroll
        for (int t = 0; t < 4; t++) {
            int i = tid + t*256;
            int m = i >> 3, k4 = (i & 7) << 2;
            cp16(aBase + (uint32_t)(m*36 + k4)*4, &Ab[(size_t)(m0+m)*K + kc + k4]);
        }
        #pragma unroll
        for (int t = 0; t < 4; t++) {
            int i = tid + t*256;
            int k = i >> 5, n4 = (i & 31) << 2;
            cp16(bBase + (uint32_t)(k*136 + n4)*4, &Bb[(size_t)(kc+k)*HW + n0 + n4]);
        }
        CP_COMMIT();
    };

    load_chunk(0, 0);

    for (int ch = 0; ch < NCH; ch++) {
        if (ch + 1 < NCH) { load_chunk(ch+1, (ch+1)&1); CP_WAIT1(); }
        else              { CP_WAIT0(); }
        __syncthreads();

        const float (*As)[36]  = (const float(*)[36])(dsm + (ch&1)*SZA);
        const float (*Bs)[136] = (const float(*)[136])(dsm + 2*SZA + (ch&1)*SZB);

        #pragma unroll
        for (int ks = 0; ks < 4; ks++) {
            const int kb = (ks << 3) + tq;
            uint32_t af[4][4];
            #pragma unroll
            for (int mt = 0; mt < 4; mt++) {
                int mb = warpM*64 + mt*16 + gq;
                af[mt][0] = __float_as_uint(As[mb  ][kb  ]);
                af[mt][1] = __float_as_uint(As[mb+8][kb  ]);
                af[mt][2] = __float_as_uint(As[mb  ][kb+4]);
                af[mt][3] = __float_as_uint(As[mb+8][kb+4]);
            }
            uint32_t bf[4][2];
            #pragma unroll
            for (int nt = 0; nt < 4; nt++) {
                int nb = warpN*32 + nt*8 + gq;
                bf[nt][0] = __float_as_uint(Bs[kb  ][nb]);
                bf[nt][1] = __float_as_uint(Bs[kb+4][nb]);
            }
            #pragma unroll
            for (int mt = 0; mt < 4; mt++)
            #pragma unroll
            for (int nt = 0; nt < 4; nt++) {
                asm volatile(
                    "mma.sync.aligned.m16n8k8.row.col.f32.tf32.tf32.f32 "
                    "{%0,%1,%2,%3}, {%4,%5,%6,%7}, {%8,%9}, {%0,%1,%2,%3};"
                    : "+f"(acc[mt][nt][0]), "+f"(acc[mt][nt][1]),
                      "+f"(acc[mt][nt][2]), "+f"(acc[mt][nt][3])
                    : "r"(af[mt][0]), "r"(af[mt][1]), "r"(af[mt][2]), "r"(af[mt][3]),
                      "r"(bf[nt][0]), "r"(bf[nt][1]));
            }
        }
        __syncthreads();
    }

    const bool rq = QROUND && (blockIdx.y == 0);   // q rows: round for GEMM2 consumption
    #pragma unroll
    for (int mt = 0; mt < 4; mt++) {
        int m1 = m0 + warpM*64 + mt*16 + gq;
        float bi1 = biasb[m1], bi2 = biasb[m1+8];
        #pragma unroll
        for (int nt = 0; nt < 4; nt++) {
            int n = n0 + warpN*32 + nt*8 + tq*2;
            float2 v1 = { acc[mt][nt][0] + bi1, acc[mt][nt][1] + bi1 };
            float2 v2 = { acc[mt][nt][2] + bi2, acc[mt][nt][3] + bi2 };
            if (rq) {
                v1.x = tf32f(v1.x); v1.y = tf32f(v1.y);
                v2.x = tf32f(v2.x); v2.y = tf32f(v2.y);
            }
            *(float2*)&Cb[(size_t)m1*HW + n]     = v1;
            *(float2*)&Cb[(size_t)(m1+8)*HW + n] = v2;
        }
    }
}

// -------- 4) context + fused softmax denominator --------
// ctx[b,h,d,e] = (sum_n exp(k[d,n]) * v[e,n]) / (sum_n exp(k[d,n]))
__global__ __launch_bounds__(1024)
void k_context() {
    int h = blockIdx.x, b = blockIdx.y;
    const int tid = threadIdx.x;
    const int d = tid >> 5, e = tid & 31;
    __shared__ float ek[32][128];
    __shared__ float vt[32][129];
    const float* kbase = g_qkv + ((size_t)(b*OQ) + HID   + h*32)*HW;
    const float* vbase = g_qkv + ((size_t)(b*OQ) + 2*HID + h*32)*HW;
    float acc = 0.f, sacc = 0.f;
    for (int n0 = 0; n0 < HW; n0 += 128) {
        #pragma unroll
        for (int i = tid; i < 4096; i += 1024) {
            int r = i >> 7, cc = i & 127;
            ek[r][cc] = expf(kbase[(size_t)r*HW + n0 + cc]);
            vt[r][cc] = vbase[(size_t)r*HW + n0 + cc];
        }
        __syncthreads();
        #pragma unroll 16
        for (int nn = 0; nn < 128; nn++) {
            float kv = ek[d][nn];
            acc  += kv * vt[e][nn];
            sacc += kv;
        }
        __syncthreads();
    }
    g_ctx[(((size_t)b*4 + h)*32 + d)*32 + e] = acc / sacc;
}

// -------- 5) fold out_w with context -> tf32-rounded g_M --------
__global__ void k_fold(const float* __restrict__ out_w) {
    int b = blockIdx.x;
    const int tid = threadIdx.x;
    __shared__ float cs[4*32*32];
    for (int i = tid; i < 4096; i += 256) cs[i] = g_ctx[(size_t)b*4096 + i];
    __syncthreads();
    int o = tid;
    const float* w = out_w + (size_t)o*HID;
    for (int h = 0; h < 4; h++) {
        float wr[32];
        #pragma unroll
        for (int e = 0; e < 32; e++) wr[e] = w[h*32 + e];
        for (int d = 0; d < 32; d++) {
            float acc = 0.f;
            #pragma unroll
            for (int e = 0; e < 32; e++) acc += wr[e] * cs[(h*32 + d)*32 + e];
            g_M[((size_t)b*CCH + o)*HID + h*32 + d] = tf32f(acc);
        }
    }
}

extern "C" void kernel_launch(void* const* d_in, const int* in_sizes, int n_in,
                              void* d_out, int out_size) {
    const float* x     = (const float*)d_in[0];
    const float* gn_w  = (const float*)d_in[1];
    const float* gn_b  = (const float*)d_in[2];
    const float* qkv_w = (const float*)d_in[3];
    const float* qkv_b = (const float*)d_in[4];
    const float* out_w = (const float*)d_in[5];
    const float* out_b = (const float*)d_in[6];
    float* out = (float*)d_out;

    float *p_xr, *p_wA, *p_qkv, *p_M, *p_bq;
    cudaGetSymbolAddress((void**)&p_xr,  g_xr);
    cudaGetSymbolAddress((void**)&p_wA,  g_wA);
    cudaGetSymbolAddress((void**)&p_qkv, g_qkv);
    cudaGetSymbolAddress((void**)&p_M,   g_M);
    cudaGetSymbolAddress((void**)&p_bq,  g_bq);

    cudaFuncSetAttribute(k_mma_gemm<true>,  cudaFuncAttributeMaxDynamicSharedMemorySize, GSMEM);
    cudaFuncSetAttribute(k_mma_gemm<false>, cudaFuncAttributeMaxDynamicSharedMemorySize, GSMEM);

    // 1) GroupNorm stats + tf32-round x
    k_gnstats<<<dim3(NGRP, BATCH), 256>>>(x, gn_w, gn_b);
    // 2) bias fold + weight prep (independent, back-to-back)
    k_biasfold<<<BATCH, 256>>>(qkv_w, qkv_b);
    k_prepw<<<dim3(OQ*CCH/1024, BATCH), 256>>>(qkv_w);
    // 3) QKV GEMM: 384x4096x256 x16
    k_mma_gemm<true><<<dim3(HW/128, OQ/128, BATCH), 256, GSMEM>>>(
        p_wA, (long)OQ*CCH, p_xr, (long)CCH*HW, p_qkv, (long)OQ*HW,
        p_bq, (long)OQ, CCH);
    // 4) context (+ fused softmax denominator)
    k_context<<<dim3(4, BATCH), 1024>>>();
    // 5) fold out_w with context
    k_fold<<<BATCH, 256>>>(out_w);
    // 6) output GEMM: 256x4096x128 x16
    k_mma_gemm<false><<<dim3(HW/128, CCH/128, BATCH), 256, GSMEM>>>(
        p_M, (long)CCH*HID, p_qkv, (long)OQ*HW, out, (long)CCH*HW,
        out_b, 0L, HID);
}

// round 12
// speedup vs baseline: 2.2668x; 1.2908x over previous
#include <cuda_runtime.h>
#include <math.h>
#include <stdint.h>

#define BATCH 16
#define CCH   256
#define HW    4096
#define OQ    384      // 3*hidden
#define HID   128
#define NGRP  32
#define CPG   8
#define EPS   1e-5f
#define NSPL  8        // context n-splits

// -------- scratch --------
__device__ float g_scale[BATCH*CCH];
__device__ float g_shift[BATCH*CCH];
__device__ float g_bq[BATCH*OQ];
__device__ float g_wA[(size_t)BATCH*OQ*CCH];    // tf32(qkv_w * scale)
__device__ float g_qkv[(size_t)BATCH*OQ*HW];    // [b][o][n] q 0..127 (tf32-rounded), k, v
__device__ float g_ctxp[BATCH*4*NSPL*32*32];    // context partials (numerator)
__device__ float g_ctxs[BATCH*4*NSPL*32];       // context partials (denominator)
__device__ float g_M[BATCH*CCH*HID];            // tf32-rounded

__device__ __forceinline__ float tf32f(float x) {
    uint32_t u;
    asm("cvt.rna.tf32.f32 %0, %1;" : "=r"(u) : "f"(x));
    return __uint_as_float(u);
}
__device__ __forceinline__ uint32_t smem_u32(const void* p) {
    uint32_t a;
    asm("{ .reg .u64 t; cvta.to.shared.u64 t, %1; cvt.u32.u64 %0, t; }" : "=r"(a) : "l"(p));
    return a;
}
__device__ __forceinline__ void cp16(uint32_t saddr, const void* gptr) {
    asm volatile("cp.async.cg.shared.global [%0], [%1], 16;" :: "r"(saddr), "l"(gptr));
}
#define CP_COMMIT() asm volatile("cp.async.commit_group;" ::: "memory")
#define CP_WAIT0()  asm volatile("cp.async.wait_group 0;" ::: "memory")

// -------- 1) GroupNorm stats (read-only pass) --------
__global__ void k_gnstats(const float* __restrict__ x,
                          const float* __restrict__ gn_w,
                          const float* __restrict__ gn_b) {
    int g = blockIdx.x, b = blockIdx.y;
    const float4* p4 = (const float4*)(x + ((size_t)b*CCH + g*CPG)*HW);
    const int n4 = CPG*HW/4;
    float s = 0.f, s2 = 0.f;
    for (int i = threadIdx.x; i < n4; i += blockDim.x) {
        float4 v = p4[i];
        s  += v.x + v.y + v.z + v.w;
        s2 += v.x*v.x + v.y*v.y + v.z*v.z + v.w*v.w;
    }
    __shared__ float ss[256], ss2[256];
    ss[threadIdx.x] = s; ss2[threadIdx.x] = s2;
    __syncthreads();
    for (int o = 128; o > 0; o >>= 1) {
        if (threadIdx.x < o) { ss[threadIdx.x] += ss[threadIdx.x+o]; ss2[threadIdx.x] += ss2[threadIdx.x+o]; }
        __syncthreads();
    }
    if (threadIdx.x < CPG) {
        const float inv = 1.0f / (float)(CPG*HW);
        float mean = ss[0] * inv;
        float var  = ss2[0] * inv - mean*mean;
        float r    = rsqrtf(var + EPS);
        int c = g*CPG + threadIdx.x;
        float a = gn_w[c] * r;
        g_scale[b*CCH + c] = a;
        g_shift[b*CCH + c] = gn_b[c] - mean*a;
    }
}

// -------- 2a) fold qkv bias --------
__global__ void k_biasfold(const float* __restrict__ qkv_w,
                           const float* __restrict__ qkv_b) {
    int b = blockIdx.x;
    __shared__ float sh[CCH];
    for (int i = threadIdx.x; i < CCH; i += blockDim.x) sh[i] = g_shift[b*CCH + i];
    __syncthreads();
    for (int o = threadIdx.x; o < OQ; o += blockDim.x) {
        const float* w = qkv_w + (size_t)o*CCH;
        float acc = 0.f;
        #pragma unroll 8
        for (int c = 0; c < CCH; c++) acc += w[c]*sh[c];
        g_bq[b*OQ + o] = qkv_b[o] + acc;
    }
}

// -------- 2b) pre-scale + tf32-round weights --------
__global__ void k_prepw(const float* __restrict__ qkv_w) {
    int b = blockIdx.y;
    int idx = (blockIdx.x*256 + threadIdx.x) * 4;
    int c = idx & (CCH-1);
    float4 w = *(const float4*)&qkv_w[idx];
    const float* sc = g_scale + b*CCH + c;
    float4 r;
    r.x = tf32f(w.x * sc[0]); r.y = tf32f(w.y * sc[1]);
    r.z = tf32f(w.z * sc[2]); r.w = tf32f(w.w * sc[3]);
    *(float4*)&g_wA[(size_t)b*OQ*CCH + idx] = r;
}

// -------- tf32 mma.sync GEMM, cp.async double-buffered, single sync/chunk --------
// CTA 128x128, BK=32, 8 warps (2x4), warp tile 64x32 = 4x4 m16n8k8.
// DOCVT: round B fragments to tf32 in-loop (B raw fp32 in gmem).
#define SZA (128*36*4)
#define SZB (32*136*4)
#define GSMEM (2*SZA + 2*SZB)
template<bool QROUND, bool DOCVT>
__global__ __launch_bounds__(256)
void k_mma_gemm(const float* __restrict__ A, long strideA,
                const float* __restrict__ Bm, long strideB,
                float* __restrict__ Cm, long strideC,
                const float* __restrict__ bias, long strideBias,
                int K) {
    extern __shared__ char dsm[];
    const uint32_t sb = smem_u32(dsm);
    const int b = blockIdx.z;
    const float* Ab = A + (size_t)b*strideA;
    const float* Bb = Bm + (size_t)b*strideB;
    float* Cb = Cm + (size_t)b*strideC;
    const float* biasb = bias + (size_t)b*strideBias;

    const int m0 = blockIdx.y * 128;
    const int n0 = blockIdx.x * 128;
    const int tid = threadIdx.x;
    const int lane = tid & 31, warp = tid >> 5;
    const int warpM = warp >> 2, warpN = warp & 3;
    const int gq = lane >> 2, tq = lane & 3;

    float acc[4][4][4];
    #pragma unroll
    for (int i = 0; i < 4; i++)
    #pragma unroll
    for (int j = 0; j < 4; j++)
    #pragma unroll
    for (int r = 0; r < 4; r++) acc[i][j][r] = 0.f;

    const int NCH = K >> 5;

    auto load_chunk = [&](int ch, int st) {
        const int kc = ch << 5;
        const uint32_t aBase = sb + st*SZA;
        const uint32_t bBase = sb + 2*SZA + st*SZB;
        #pragma unroll
        for (int t = 0; t < 4; t++) {
            int i = tid + t*256;
            int m = i >> 3, k4 = (i & 7) << 2;
            cp16(aBase + (uint32_t)(m*36 + k4)*4, &Ab[(size_t)(m0+m)*K + kc + k4]);
        }
        #pragma unroll
        for (int t = 0; t < 4; t++) {
            int i = tid + t*256;
            int k = i >> 5, n4 = (i & 31) << 2;
            cp16(bBase + (uint32_t)(k*136 + n4)*4, &Bb[(size_t)(kc+k)*HW + n0 + n4]);
        }
        CP_COMMIT();
    };

    load_chunk(0, 0);

    for (int ch = 0; ch < NCH; ch++) {
        CP_WAIT0();
        __syncthreads();                 // data ready + all warps done with other buffer
        if (ch + 1 < NCH) load_chunk(ch+1, (ch+1)&1);

        const float (*As)[36]  = (const float(*)[36])(dsm + (ch&1)*SZA);
        const float (*Bs)[136] = (const float(*)[136])(dsm + 2*SZA + (ch&1)*SZB);

        #pragma unroll
        for (int ks = 0; ks < 4; ks++) {
            const int kb = (ks << 3) + tq;
            uint32_t af[4][4];
            #pragma unroll
            for (int mt = 0; mt < 4; mt++) {
                int mb = warpM*64 + mt*16 + gq;
                af[mt][0] = __float_as_uint(As[mb  ][kb  ]);
                af[mt][1] = __float_as_uint(As[mb+8][kb  ]);
                af[mt][2] = __float_as_uint(As[mb  ][kb+4]);
                af[mt][3] = __float_as_uint(As[mb+8][kb+4]);
            }
            uint32_t bf[4][2];
            #pragma unroll
            for (int nt = 0; nt < 4; nt++) {
                int nb = warpN*32 + nt*8 + gq;
                float b0 = Bs[kb  ][nb], b1 = Bs[kb+4][nb];
                if (DOCVT) { b0 = tf32f(b0); b1 = tf32f(b1); }
                bf[nt][0] = __float_as_uint(b0);
                bf[nt][1] = __float_as_uint(b1);
            }
            #pragma unroll
            for (int mt = 0; mt < 4; mt++)
            #pragma unroll
            for (int nt = 0; nt < 4; nt++) {
                asm volatile(
                    "mma.sync.aligned.m16n8k8.row.col.f32.tf32.tf32.f32 "
                    "{%0,%1,%2,%3}, {%4,%5,%6,%7}, {%8,%9}, {%0,%1,%2,%3};"
                    : "+f"(acc[mt][nt][0]), "+f"(acc[mt][nt][1]),
                      "+f"(acc[mt][nt][2]), "+f"(acc[mt][nt][3])
                    : "r"(af[mt][0]), "r"(af[mt][1]), "r"(af[mt][2]), "r"(af[mt][3]),
                      "r"(bf[nt][0]), "r"(bf[nt][1]));
            }
        }
    }

    __syncthreads();   // all MMA reads done before epilogue reuses nothing; keeps cp.async state clean
    const bool rq = QROUND && (blockIdx.y == 0);
    #pragma unroll
    for (int mt = 0; mt < 4; mt++) {
        int m1 = m0 + warpM*64 + mt*16 + gq;
        float bi1 = biasb[m1], bi2 = biasb[m1+8];
        #pragma unroll
        for (int nt = 0; nt < 4; nt++) {
            int n = n0 + warpN*32 + nt*8 + tq*2;
            float2 v1 = { acc[mt][nt][0] + bi1, acc[mt][nt][1] + bi1 };
            float2 v2 = { acc[mt][nt][2] + bi2, acc[mt][nt][3] + bi2 };
            if (rq) {
                v1.x = tf32f(v1.x); v1.y = tf32f(v1.y);
                v2.x = tf32f(v2.x); v2.y = tf32f(v2.y);
            }
            *(float2*)&Cb[(size_t)m1*HW + n]     = v1;
            *(float2*)&Cb[(size_t)(m1+8)*HW + n] = v2;
        }
    }
}

// -------- 4) context partials: 8-way n-split --------
// partial[b,h,s,d,e] = sum_{n in split s} exp(k[d,n]) * v[e,n]; dens[b,h,s,d] = sum exp(k[d,n])
__global__ __launch_bounds__(1024)
void k_context() {
    int h = blockIdx.x, b = blockIdx.y, s = blockIdx.z;
    const int tid = threadIdx.x;
    const int d = tid >> 5, e = tid & 31;
    __shared__ float ek[32][128];
    __shared__ float vt[32][129];
    const float* kbase = g_qkv + ((size_t)(b*OQ) + HID   + h*32)*HW;
    const float* vbase = g_qkv + ((size_t)(b*OQ) + 2*HID + h*32)*HW;
    float acc = 0.f, sacc = 0.f;
    const int nlo = s * (HW/NSPL);
    for (int n0 = nlo; n0 < nlo + HW/NSPL; n0 += 128) {
        #pragma unroll
        for (int i = tid; i < 4096; i += 1024) {
            int r = i >> 7, cc = i & 127;
            ek[r][cc] = __expf(kbase[(size_t)r*HW + n0 + cc]);
            vt[r][cc] = vbase[(size_t)r*HW + n0 + cc];
        }
        __syncthreads();
        #pragma unroll 16
        for (int nn = 0; nn < 128; nn++) {
            float kv = ek[d][nn];
            acc  += kv * vt[e][nn];
            sacc += kv;
        }
        __syncthreads();
    }
    int bh = b*4 + h;
    g_ctxp[(((size_t)bh*NSPL + s)*32 + d)*32 + e] = acc;
    if (e == 0) g_ctxs[((size_t)bh*NSPL + s)*32 + d] = sacc;
}

// -------- 5) reduce partials + fold out_w -> tf32-rounded g_M --------
__global__ void k_fold(const float* __restrict__ out_w) {
    int b = blockIdx.x;
    const int tid = threadIdx.x;
    __shared__ float cs[4*32*32];
    __shared__ float den[128];
    if (tid < 128) {
        int h = tid >> 5, d = tid & 31;
        float t = 0.f;
        #pragma unroll
        for (int s = 0; s < NSPL; s++) t += g_ctxs[(((size_t)(b*4+h))*NSPL + s)*32 + d];
        den[tid] = 1.0f / t;
    }
    __syncthreads();
    for (int i = tid; i < 4096; i += 256) {
        int h = i >> 10, rem = i & 1023;
        float t = 0.f;
        #pragma unroll
        for (int s = 0; s < NSPL; s++) t += g_ctxp[(((size_t)(b*4+h))*NSPL + s)*1024 + rem];
        cs[i] = t * den[i >> 5];
    }
    __syncthreads();
    int o = tid;
    const float* w = out_w + (size_t)o*HID;
    for (int h = 0; h < 4; h++) {
        float wr[32];
        #pragma unroll
        for (int e = 0; e < 32; e++) wr[e] = w[h*32 + e];
        for (int d = 0; d < 32; d++) {
            float acc = 0.f;
            #pragma unroll
            for (int e = 0; e < 32; e++) acc += wr[e] * cs[(h*32 + d)*32 + e];
            g_M[((size_t)b*CCH + o)*HID + h*32 + d] = tf32f(acc);
        }
    }
}

extern "C" void kernel_launch(void* const* d_in, const int* in_sizes, int n_in,
                              void* d_out, int out_size) {
    const float* x     = (const float*)d_in[0];
    const float* gn_w  = (const float*)d_in[1];
    const float* gn_b  = (const float*)d_in[2];
    const float* qkv_w = (const float*)d_in[3];
    const float* qkv_b = (const float*)d_in[4];
    const float* out_w = (const float*)d_in[5];
    const float* out_b = (const float*)d_in[6];
    float* out = (float*)d_out;

    float *p_wA, *p_qkv, *p_M, *p_bq;
    cudaGetSymbolAddress((void**)&p_wA,  g_wA);
    cudaGetSymbolAddress((void**)&p_qkv, g_qkv);
    cudaGetSymbolAddress((void**)&p_M,   g_M);
    cudaGetSymbolAddress((void**)&p_bq,  g_bq);

    cudaFuncSetAttribute((const void*)k_mma_gemm<true,true>,   cudaFuncAttributeMaxDynamicSharedMemorySize, GSMEM);
    cudaFuncSetAttribute((const void*)k_mma_gemm<false,false>, cudaFuncAttributeMaxDynamicSharedMemorySize, GSMEM);

    // 1) GroupNorm stats
    k_gnstats<<<dim3(NGRP, BATCH), 256>>>(x, gn_w, gn_b);
    // 2) bias fold + weight prep
    k_biasfold<<<BATCH, 256>>>(qkv_w, qkv_b);
    k_prepw<<<dim3(OQ*CCH/1024, BATCH), 256>>>(qkv_w);
    // 3) QKV GEMM (B = x raw, rounded in-loop): 384x4096x256 x16
    k_mma_gemm<true,true><<<dim3(HW/128, OQ/128, BATCH), 256, GSMEM>>>(
        p_wA, (long)OQ*CCH, x, (long)CCH*HW, p_qkv, (long)OQ*HW,
        p_bq, (long)OQ, CCH);
    // 4) context partials (8-way n-split)
    k_context<<<dim3(4, BATCH, NSPL), 1024>>>();
    // 5) reduce + fold out_w
    k_fold<<<BATCH, 256>>>(out_w);
    // 6) output GEMM (B = q rows, pre-rounded): 256x4096x128 x16
    k_mma_gemm<false,false><<<dim3(HW/128, CCH/128, BATCH), 256, GSMEM>>>(
        p_M, (long)CCH*HID, p_qkv, (long)OQ*HW, out, (long)CCH*HW,
        out_b, 0L, HID);
}

// round 13
// speedup vs baseline: 2.7582x; 1.2168x over previous
#include <cuda_runtime.h>
#include <math.h>
#include <stdint.h>

#define BATCH 16
#define CCH   256
#define HW    4096
#define OQ    384      // 3*hidden
#define HID   128
#define NGRP  32
#define CPG   8
#define EPS   1e-5f
#define NSPL  8        // context n-splits

// -------- scratch --------
__device__ float g_scale[BATCH*CCH];
__device__ float g_shift[BATCH*CCH];
__device__ float g_bq[BATCH*OQ];
__device__ float g_wA[(size_t)BATCH*OQ*CCH];    // tf32(qkv_w * scale)
__device__ float g_qkv[(size_t)BATCH*OQ*HW];    // [b][o][n] q(0..127,tf32), exp(k)(128..255), v(256..383)
__device__ float g_ctxp[BATCH*4*NSPL*32*32];    // context partials (numerator)
__device__ float g_ctxs[BATCH*4*NSPL*32];       // context partials (denominator)
__device__ float g_M[BATCH*CCH*HID];            // tf32-rounded

__device__ __forceinline__ float tf32f(float x) {
    uint32_t u;
    asm("cvt.rna.tf32.f32 %0, %1;" : "=r"(u) : "f"(x));
    return __uint_as_float(u);
}
__device__ __forceinline__ uint32_t smem_u32(const void* p) {
    uint32_t a;
    asm("{ .reg .u64 t; cvta.to.shared.u64 t, %1; cvt.u32.u64 %0, t; }" : "=r"(a) : "l"(p));
    return a;
}
__device__ __forceinline__ void cp16(uint32_t saddr, const void* gptr) {
    asm volatile("cp.async.cg.shared.global [%0], [%1], 16;" :: "r"(saddr), "l"(gptr));
}
#define CP_COMMIT() asm volatile("cp.async.commit_group;" ::: "memory")
#define CP_WAIT0()  asm volatile("cp.async.wait_group 0;" ::: "memory")

// -------- 1) GroupNorm stats --------
__global__ void k_gnstats(const float* __restrict__ x,
                          const float* __restrict__ gn_w,
                          const float* __restrict__ gn_b) {
    int g = blockIdx.x, b = blockIdx.y;
    const float4* p4 = (const float4*)(x + ((size_t)b*CCH + g*CPG)*HW);
    const int n4 = CPG*HW/4;
    float s = 0.f, s2 = 0.f;
    for (int i = threadIdx.x; i < n4; i += blockDim.x) {
        float4 v = p4[i];
        s  += v.x + v.y + v.z + v.w;
        s2 += v.x*v.x + v.y*v.y + v.z*v.z + v.w*v.w;
    }
    __shared__ float ss[256], ss2[256];
    ss[threadIdx.x] = s; ss2[threadIdx.x] = s2;
    __syncthreads();
    for (int o = 128; o > 0; o >>= 1) {
        if (threadIdx.x < o) { ss[threadIdx.x] += ss[threadIdx.x+o]; ss2[threadIdx.x] += ss2[threadIdx.x+o]; }
        __syncthreads();
    }
    if (threadIdx.x < CPG) {
        const float inv = 1.0f / (float)(CPG*HW);
        float mean = ss[0] * inv;
        float var  = ss2[0] * inv - mean*mean;
        float r    = rsqrtf(var + EPS);
        int c = g*CPG + threadIdx.x;
        float a = gn_w[c] * r;
        g_scale[b*CCH + c] = a;
        g_shift[b*CCH + c] = gn_b[c] - mean*a;
    }
}

// -------- 2a) fold qkv bias --------
__global__ void k_biasfold(const float* __restrict__ qkv_w,
                           const float* __restrict__ qkv_b) {
    int b = blockIdx.x;
    __shared__ float sh[CCH];
    for (int i = threadIdx.x; i < CCH; i += blockDim.x) sh[i] = g_shift[b*CCH + i];
    __syncthreads();
    for (int o = threadIdx.x; o < OQ; o += blockDim.x) {
        const float* w = qkv_w + (size_t)o*CCH;
        float acc = 0.f;
        #pragma unroll 8
        for (int c = 0; c < CCH; c++) acc += w[c]*sh[c];
        g_bq[b*OQ + o] = qkv_b[o] + acc;
    }
}

// -------- 2b) pre-scale + tf32-round weights --------
__global__ void k_prepw(const float* __restrict__ qkv_w) {
    int b = blockIdx.y;
    int idx = (blockIdx.x*256 + threadIdx.x) * 4;
    int c = idx & (CCH-1);
    float4 w = *(const float4*)&qkv_w[idx];
    const float* sc = g_scale + b*CCH + c;
    float4 r;
    r.x = tf32f(w.x * sc[0]); r.y = tf32f(w.y * sc[1]);
    r.z = tf32f(w.z * sc[2]); r.w = tf32f(w.w * sc[3]);
    *(float4*)&g_wA[(size_t)b*OQ*CCH + idx] = r;
}

// -------- tf32 mma.sync GEMM, cp.async double-buffered, single sync/chunk --------
// CTA 128x128, BK=32, 8 warps (2x4), warp tile 64x32 = 4x4 m16n8k8.
// MODE=1 (GEMM1): round B frags to tf32 in-loop; epilogue by blockIdx.y:
//   y==0 (q rows): tf32-round;  y==1 (k rows): __expf;  y==2 (v rows): plain.
// MODE=0 (GEMM2): plain.
#define SZA (128*36*4)
#define SZB (32*136*4)
#define GSMEM (2*SZA + 2*SZB)
template<int MODE>
__global__ __launch_bounds__(256, 2)
void k_mma_gemm(const float* __restrict__ A, long strideA,
                const float* __restrict__ Bm, long strideB,
                float* __restrict__ Cm, long strideC,
                const float* __restrict__ bias, long strideBias,
                int K) {
    extern __shared__ char dsm[];
    const uint32_t sb = smem_u32(dsm);
    const int b = blockIdx.z;
    const float* Ab = A + (size_t)b*strideA;
    const float* Bb = Bm + (size_t)b*strideB;
    float* Cb = Cm + (size_t)b*strideC;
    const float* biasb = bias + (size_t)b*strideBias;

    const int m0 = blockIdx.y * 128;
    const int n0 = blockIdx.x * 128;
    const int tid = threadIdx.x;
    const int lane = tid & 31, warp = tid >> 5;
    const int warpM = warp >> 2, warpN = warp & 3;
    const int gq = lane >> 2, tq = lane & 3;

    float acc[4][4][4];
    #pragma unroll
    for (int i = 0; i < 4; i++)
    #pragma unroll
    for (int j = 0; j < 4; j++)
    #pragma unroll
    for (int r = 0; r < 4; r++) acc[i][j][r] = 0.f;

    const int NCH = K >> 5;

    auto load_chunk = [&](int ch, int st) {
        const int kc = ch << 5;
        const uint32_t aBase = sb + st*SZA;
        const uint32_t bBase = sb + 2*SZA + st*SZB;
        #pragma unroll
        for (int t = 0; t < 4; t++) {
            int i = tid + t*256;
            int m = i >> 3, k4 = (i & 7) << 2;
            cp16(aBase + (uint32_t)(m*36 + k4)*4, &Ab[(size_t)(m0+m)*K + kc + k4]);
        }
        #pragma unroll
        for (int t = 0; t < 4; t++) {
            int i = tid + t*256;
            int k = i >> 5, n4 = (i & 31) << 2;
            cp16(bBase + (uint32_t)(k*136 + n4)*4, &Bb[(size_t)(kc+k)*HW + n0 + n4]);
        }
        CP_COMMIT();
    };

    load_chunk(0, 0);

    for (int ch = 0; ch < NCH; ch++) {
        CP_WAIT0();
        __syncthreads();
        if (ch + 1 < NCH) load_chunk(ch+1, (ch+1)&1);

        const float (*As)[36]  = (const float(*)[36])(dsm + (ch&1)*SZA);
        const float (*Bs)[136] = (const float(*)[136])(dsm + 2*SZA + (ch&1)*SZB);

        #pragma unroll
        for (int ks = 0; ks < 4; ks++) {
            const int kb = (ks << 3) + tq;
            uint32_t af[4][4];
            #pragma unroll
            for (int mt = 0; mt < 4; mt++) {
                int mb = warpM*64 + mt*16 + gq;
                af[mt][0] = __float_as_uint(As[mb  ][kb  ]);
                af[mt][1] = __float_as_uint(As[mb+8][kb  ]);
                af[mt][2] = __float_as_uint(As[mb  ][kb+4]);
                af[mt][3] = __float_as_uint(As[mb+8][kb+4]);
            }
            uint32_t bf[4][2];
            #pragma unroll
            for (int nt = 0; nt < 4; nt++) {
                int nb = warpN*32 + nt*8 + gq;
                float b0 = Bs[kb  ][nb], b1 = Bs[kb+4][nb];
                if (MODE == 1) { b0 = tf32f(b0); b1 = tf32f(b1); }
                bf[nt][0] = __float_as_uint(b0);
                bf[nt][1] = __float_as_uint(b1);
            }
            #pragma unroll
            for (int mt = 0; mt < 4; mt++)
            #pragma unroll
            for (int nt = 0; nt < 4; nt++) {
                asm volatile(
                    "mma.sync.aligned.m16n8k8.row.col.f32.tf32.tf32.f32 "
                    "{%0,%1,%2,%3}, {%4,%5,%6,%7}, {%8,%9}, {%0,%1,%2,%3};"
                    : "+f"(acc[mt][nt][0]), "+f"(acc[mt][nt][1]),
                      "+f"(acc[mt][nt][2]), "+f"(acc[mt][nt][3])
                    : "r"(af[mt][0]), "r"(af[mt][1]), "r"(af[mt][2]), "r"(af[mt][3]),
                      "r"(bf[nt][0]), "r"(bf[nt][1]));
            }
        }
    }

    __syncthreads();
    const int emode = (MODE == 1) ? blockIdx.y : 2;   // 0=round(q), 1=exp(k), 2=plain
    #pragma unroll
    for (int mt = 0; mt < 4; mt++) {
        int m1 = m0 + warpM*64 + mt*16 + gq;
        float bi1 = biasb[m1], bi2 = biasb[m1+8];
        #pragma unroll
        for (int nt = 0; nt < 4; nt++) {
            int n = n0 + warpN*32 + nt*8 + tq*2;
            float2 v1 = { acc[mt][nt][0] + bi1, acc[mt][nt][1] + bi1 };
            float2 v2 = { acc[mt][nt][2] + bi2, acc[mt][nt][3] + bi2 };
            if (emode == 0) {
                v1.x = tf32f(v1.x); v1.y = tf32f(v1.y);
                v2.x = tf32f(v2.x); v2.y = tf32f(v2.y);
            } else if (emode == 1) {
                v1.x = __expf(v1.x); v1.y = __expf(v1.y);
                v2.x = __expf(v2.x); v2.y = __expf(v2.y);
            }
            *(float2*)&Cb[(size_t)m1*HW + n]     = v1;
            *(float2*)&Cb[(size_t)(m1+8)*HW + n] = v2;
        }
    }
}

// -------- 4) context partials: 8-way n-split, 2x2 register blocking --------
// k rows hold exp(k) already. partial[b,h,s,d,e] = sum_n ek[d,n]*v[e,n]; dens = sum_n ek[d,n]
__global__ __launch_bounds__(256)
void k_context() {
    int h = blockIdx.x, b = blockIdx.y, s = blockIdx.z;
    const int tid = threadIdx.x;
    const int d0 = (tid >> 4) << 1;      // 0,2,...,30
    const int e0 = (tid & 15) << 1;      // 0,2,...,30
    __shared__ float ek[32][129];
    __shared__ float vt[32][129];
    const float* kbase = g_qkv + ((size_t)(b*OQ) + HID   + h*32)*HW;
    const float* vbase = g_qkv + ((size_t)(b*OQ) + 2*HID + h*32)*HW;
    float a00 = 0.f, a01 = 0.f, a10 = 0.f, a11 = 0.f, s0 = 0.f, s1 = 0.f;
    const int nlo = s * (HW/NSPL);
    for (int n0 = nlo; n0 < nlo + HW/NSPL; n0 += 128) {
        #pragma unroll
        for (int i = tid; i < 1024; i += 256) {
            int r = i >> 5, c4 = (i & 31) << 2;
            float4 kv = *(const float4*)&kbase[(size_t)r*HW + n0 + c4];
            float4 vv = *(const float4*)&vbase[(size_t)r*HW + n0 + c4];
            ek[r][c4] = kv.x; ek[r][c4+1] = kv.y; ek[r][c4+2] = kv.z; ek[r][c4+3] = kv.w;
            vt[r][c4] = vv.x; vt[r][c4+1] = vv.y; vt[r][c4+2] = vv.z; vt[r][c4+3] = vv.w;
        }
        __syncthreads();
        #pragma unroll 8
        for (int nn = 0; nn < 128; nn++) {
            float k0 = ek[d0][nn], k1 = ek[d0+1][nn];
            float v0 = vt[e0][nn], v1 = vt[e0+1][nn];
            a00 += k0*v0; a01 += k0*v1;
            a10 += k1*v0; a11 += k1*v1;
            s0 += k0; s1 += k1;
        }
        __syncthreads();
    }
    size_t base = ((size_t)(b*4 + h)*NSPL + s) * 32;
    g_ctxp[(base + d0  )*32 + e0  ] = a00;
    g_ctxp[(base + d0  )*32 + e0+1] = a01;
    g_ctxp[(base + d0+1)*32 + e0  ] = a10;
    g_ctxp[(base + d0+1)*32 + e0+1] = a11;
    if (e0 == 0) { g_ctxs[base + d0] = s0; g_ctxs[base + d0+1] = s1; }
}

// -------- 5) reduce partials + fold out_w -> tf32-rounded g_M, per (b,h) --------
__global__ void k_fold(const float* __restrict__ out_w) {
    int b = blockIdx.x, h = blockIdx.y;
    const int tid = threadIdx.x;
    __shared__ float cs[1024];
    __shared__ float den[32];
    const size_t pbase = (size_t)(b*4 + h)*NSPL;
    for (int i = tid; i < 1024; i += 256) {
        float t = 0.f;
        #pragma unroll
        for (int sp = 0; sp < NSPL; sp++) t += g_ctxp[(pbase + sp)*1024 + i];
        cs[i] = t;
    }
    if (tid < 32) {
        float t = 0.f;
        #pragma unroll
        for (int sp = 0; sp < NSPL; sp++) t += g_ctxs[(pbase + sp)*32 + tid];
        den[tid] = 1.0f / t;
    }
    __syncthreads();
    int o = tid;
    const float* w = out_w + (size_t)o*HID + h*32;
    float wr[32];
    #pragma unroll
    for (int e = 0; e < 32; e++) wr[e] = w[e];
    for (int d = 0; d < 32; d++) {
        float acc = 0.f;
        #pragma unroll
        for (int e = 0; e < 32; e++) acc += wr[e] * cs[d*32 + e];
        g_M[((size_t)b*CCH + o)*HID + h*32 + d] = tf32f(acc * den[d]);
    }
}

extern "C" void kernel_launch(void* const* d_in, const int* in_sizes, int n_in,
                              void* d_out, int out_size) {
    const float* x     = (const float*)d_in[0];
    const float* gn_w  = (const float*)d_in[1];
    const float* gn_b  = (const float*)d_in[2];
    const float* qkv_w = (const float*)d_in[3];
    const float* qkv_b = (const float*)d_in[4];
    const float* out_w = (const float*)d_in[5];
    const float* out_b = (const float*)d_in[6];
    float* out = (float*)d_out;

    float *p_wA, *p_qkv, *p_M, *p_bq;
    cudaGetSymbolAddress((void**)&p_wA,  g_wA);
    cudaGetSymbolAddress((void**)&p_qkv, g_qkv);
    cudaGetSymbolAddress((void**)&p_M,   g_M);
    cudaGetSymbolAddress((void**)&p_bq,  g_bq);

    cudaFuncSetAttribute((const void*)k_mma_gemm<1>, cudaFuncAttributeMaxDynamicSharedMemorySize, GSMEM);
    cudaFuncSetAttribute((const void*)k_mma_gemm<0>, cudaFuncAttributeMaxDynamicSharedMemorySize, GSMEM);

    // 1) GroupNorm stats
    k_gnstats<<<dim3(NGRP, BATCH), 256>>>(x, gn_w, gn_b);
    // 2) bias fold + weight prep
    k_biasfold<<<BATCH, 256>>>(qkv_w, qkv_b);
    k_prepw<<<dim3(OQ*CCH/1024, BATCH), 256>>>(qkv_w);
    // 3) QKV GEMM (B = x raw, rounded in-loop; epilogue q-round/k-exp): 384x4096x256 x16
    k_mma_gemm<1><<<dim3(HW/128, OQ/128, BATCH), 256, GSMEM>>>(
        p_wA, (long)OQ*CCH, x, (long)CCH*HW, p_qkv, (long)OQ*HW,
        p_bq, (long)OQ, CCH);
    // 4) context partials (8-way n-split, 2x2 blocking)
    k_context<<<dim3(4, BATCH, NSPL), 256>>>();
    // 5) reduce + fold out_w, per (b,h)
    k_fold<<<dim3(BATCH, 4), 256>>>(out_w);
    // 6) output GEMM: 256x4096x128 x16
    k_mma_gemm<0><<<dim3(HW/128, CCH/128, BATCH), 256, GSMEM>>>(
        p_M, (long)CCH*HID, p_qkv, (long)OQ*HW, out, (long)CCH*HW,
        out_b, 0L, HID);
}

// round 14
// speedup vs baseline: 3.2995x; 1.1963x over previous
#include <cuda_runtime.h>
#include <math.h>
#include <stdint.h>

#define BATCH 16
#define CCH   256
#define HW    4096
#define OQ    384      // 3*hidden
#define HID   128
#define NGRP  32
#define CPG   8
#define EPS   1e-5f
#define NSPL  8        // context n-splits

// -------- scratch --------
__device__ float g_scale[BATCH*CCH];
__device__ float g_shift[BATCH*CCH];
__device__ float g_bq[BATCH*OQ];
__device__ float g_wA[(size_t)BATCH*OQ*CCH];    // fragment-major tf32(qkv_w*scale)
__device__ float g_qkv[(size_t)BATCH*OQ*HW];    // [b][o][n] q(tf32) 0..127, exp(k) 128..255, v 256..383
__device__ float g_ctxp[BATCH*4*NSPL*32*32];
__device__ float g_ctxs[BATCH*4*NSPL*32];
__device__ float g_M[BATCH*CCH*HID];            // fragment-major tf32

__device__ __forceinline__ float tf32f(float x) {
    uint32_t u;
    asm("cvt.rna.tf32.f32 %0, %1;" : "=r"(u) : "f"(x));
    return __uint_as_float(u);
}
__device__ __forceinline__ uint32_t smem_u32(const void* p) {
    uint32_t a;
    asm("{ .reg .u64 t; cvta.to.shared.u64 t, %1; cvt.u32.u64 %0, t; }" : "=r"(a) : "l"(p));
    return a;
}
__device__ __forceinline__ void cp16(uint32_t saddr, const void* gptr) {
    asm volatile("cp.async.cg.shared.global [%0], [%1], 16;" :: "r"(saddr), "l"(gptr));
}
#define CP_COMMIT() asm volatile("cp.async.commit_group;" ::: "memory")
#define CP_WAIT0()  asm volatile("cp.async.wait_group 0;" ::: "memory")

// -------- 1) GroupNorm stats --------
__global__ void k_gnstats(const float* __restrict__ x,
                          const float* __restrict__ gn_w,
                          const float* __restrict__ gn_b) {
    int g = blockIdx.x, b = blockIdx.y;
    const float4* p4 = (const float4*)(x + ((size_t)b*CCH + g*CPG)*HW);
    const int n4 = CPG*HW/4;
    float s = 0.f, s2 = 0.f;
    for (int i = threadIdx.x; i < n4; i += blockDim.x) {
        float4 v = p4[i];
        s  += v.x + v.y + v.z + v.w;
        s2 += v.x*v.x + v.y*v.y + v.z*v.z + v.w*v.w;
    }
    __shared__ float ss[256], ss2[256];
    ss[threadIdx.x] = s; ss2[threadIdx.x] = s2;
    __syncthreads();
    for (int o = 128; o > 0; o >>= 1) {
        if (threadIdx.x < o) { ss[threadIdx.x] += ss[threadIdx.x+o]; ss2[threadIdx.x] += ss2[threadIdx.x+o]; }
        __syncthreads();
    }
    if (threadIdx.x < CPG) {
        const float inv = 1.0f / (float)(CPG*HW);
        float mean = ss[0] * inv;
        float var  = ss2[0] * inv - mean*mean;
        float r    = rsqrtf(var + EPS);
        int c = g*CPG + threadIdx.x;
        float a = gn_w[c] * r;
        g_scale[b*CCH + c] = a;
        g_shift[b*CCH + c] = gn_b[c] - mean*a;
    }
}

// -------- 2a) fold qkv bias --------
__global__ void k_biasfold(const float* __restrict__ qkv_w,
                           const float* __restrict__ qkv_b) {
    int b = blockIdx.x;
    __shared__ float sh[CCH];
    for (int i = threadIdx.x; i < CCH; i += blockDim.x) sh[i] = g_shift[b*CCH + i];
    __syncthreads();
    int o = blockIdx.y*128 + threadIdx.x;
    if (threadIdx.x < 128) {
        const float* w = qkv_w + (size_t)o*CCH;
        float acc = 0.f;
        #pragma unroll 8
        for (int c = 0; c < CCH; c++) acc += w[c]*sh[c];
        g_bq[b*OQ + o] = qkv_b[o] + acc;
    }
}

// -------- 2b) prep weights: scale + tf32-round + permute to fragment-major --------
// layout per batch: [ot(3)][ch(8)][wm(2)][mt(4)][ks(4)][lane(32)][4]
__global__ void k_prepw(const float* __restrict__ qkv_w) {
    int b = blockIdx.y;
    int f4 = blockIdx.x*256 + threadIdx.x;           // 0..24575
    int lane = f4 & 31;
    int t1 = f4 >> 5;
    int ks = t1 & 3;  int t2 = t1 >> 2;
    int mt = t2 & 3;  int t3 = t2 >> 2;
    int wm = t3 & 1;  int t4 = t3 >> 1;
    int ch = t4 & 7;  int ot = t4 >> 3;
    int gq = lane >> 2, tq = lane & 3;
    int o = ot*128 + wm*64 + mt*16 + gq;
    int c = ch*32 + ks*8 + tq;
    const float* sc = g_scale + b*CCH;
    float4 r;
    r.x = tf32f(qkv_w[(size_t)o*CCH + c]       * sc[c]);
    r.y = tf32f(qkv_w[(size_t)(o+8)*CCH + c]   * sc[c]);
    r.z = tf32f(qkv_w[(size_t)o*CCH + c+4]     * sc[c+4]);
    r.w = tf32f(qkv_w[(size_t)(o+8)*CCH + c+4] * sc[c+4]);
    *(float4*)&g_wA[((size_t)b*24576 + f4)*4] = r;
}

// -------- tf32 mma.sync GEMM, cp.async double-buffered, fragment-major A --------
// CTA 128x128, BK=32, 8 warps (2x4), warp tile 64x32 = 4x4 m16n8k8.
// A gmem layout: [b][Mtiles][NCH chunks][4096 floats fragment-major]
// MODE=1 (GEMM1): round B frags in-loop; epilogue y==0 round(q), y==1 exp(k), y==2 plain.
#define SZA (4096*4)
#define SZB (32*136*4)
#define GSMEM (2*SZA + 2*SZB)
template<int MODE>
__global__ __launch_bounds__(256, 2)
void k_mma_gemm(const float* __restrict__ A,
                const float* __restrict__ Bm, long strideB,
                float* __restrict__ Cm, long strideC,
                const float* __restrict__ bias, long strideBias,
                int K) {
    extern __shared__ char dsm[];
    const uint32_t sb = smem_u32(dsm);
    const int b = blockIdx.z;
    const int NCH = K >> 5;
    const float* Afrag = A + ((size_t)(b*gridDim.y + blockIdx.y)*NCH)*4096;
    const float* Bb = Bm + (size_t)b*strideB;
    float* Cb = Cm + (size_t)b*strideC;
    const float* biasb = bias + (size_t)b*strideBias;

    const int m0 = blockIdx.y * 128;
    const int n0 = blockIdx.x * 128;
    const int tid = threadIdx.x;
    const int lane = tid & 31, warp = tid >> 5;
    const int warpM = warp >> 2, warpN = warp & 3;
    const int gq = lane >> 2, tq = lane & 3;

    float acc[4][4][4];
    #pragma unroll
    for (int i = 0; i < 4; i++)
    #pragma unroll
    for (int j = 0; j < 4; j++)
    #pragma unroll
    for (int r = 0; r < 4; r++) acc[i][j][r] = 0.f;

    auto load_chunk = [&](int ch, int st) {
        const uint32_t aBase = sb + st*SZA;
        const uint32_t bBase = sb + 2*SZA + st*SZB;
        const float* Asrc = Afrag + (size_t)ch*4096;
        #pragma unroll
        for (int t = 0; t < 4; t++) {
            int i = tid + t*256;
            cp16(aBase + (uint32_t)i*16, Asrc + i*4);
        }
        const int kc = ch << 5;
        #pragma unroll
        for (int t = 0; t < 4; t++) {
            int i = tid + t*256;
            int k = i >> 5, n4 = (i & 31) << 2;
            cp16(bBase + (uint32_t)(k*136 + n4)*4, &Bb[(size_t)(kc+k)*HW + n0 + n4]);
        }
        CP_COMMIT();
    };

    load_chunk(0, 0);

    for (int ch = 0; ch < NCH; ch++) {
        CP_WAIT0();
        __syncthreads();
        if (ch + 1 < NCH) load_chunk(ch+1, (ch+1)&1);

        const float* As = (const float*)(dsm + (ch&1)*SZA);
        const float (*Bs)[136] = (const float(*)[136])(dsm + 2*SZA + (ch&1)*SZB);

        #pragma unroll
        for (int ks = 0; ks < 4; ks++) {
            const int kb = (ks << 3) + tq;
            float4 af[4];
            #pragma unroll
            for (int mt = 0; mt < 4; mt++)
                af[mt] = *(const float4*)&As[((((warpM*4 + mt)*4 + ks)*32) + lane)*4];
            uint32_t bf[4][2];
            #pragma unroll
            for (int nt = 0; nt < 4; nt++) {
                int nb = warpN*32 + nt*8 + gq;
                float b0 = Bs[kb  ][nb], b1 = Bs[kb+4][nb];
                if (MODE == 1) { b0 = tf32f(b0); b1 = tf32f(b1); }
                bf[nt][0] = __float_as_uint(b0);
                bf[nt][1] = __float_as_uint(b1);
            }
            #pragma unroll
            for (int mt = 0; mt < 4; mt++)
            #pragma unroll
            for (int nt = 0; nt < 4; nt++) {
                asm volatile(
                    "mma.sync.aligned.m16n8k8.row.col.f32.tf32.tf32.f32 "
                    "{%0,%1,%2,%3}, {%4,%5,%6,%7}, {%8,%9}, {%0,%1,%2,%3};"
                    : "+f"(acc[mt][nt][0]), "+f"(acc[mt][nt][1]),
                      "+f"(acc[mt][nt][2]), "+f"(acc[mt][nt][3])
                    : "r"(__float_as_uint(af[mt].x)), "r"(__float_as_uint(af[mt].y)),
                      "r"(__float_as_uint(af[mt].z)), "r"(__float_as_uint(af[mt].w)),
                      "r"(bf[nt][0]), "r"(bf[nt][1]));
            }
        }
    }

    __syncthreads();
    const int emode = (MODE == 1) ? blockIdx.y : 2;
    #pragma unroll
    for (int mt = 0; mt < 4; mt++) {
        int m1 = m0 + warpM*64 + mt*16 + gq;
        float bi1 = biasb[m1], bi2 = biasb[m1+8];
        #pragma unroll
        for (int nt = 0; nt < 4; nt++) {
            int n = n0 + warpN*32 + nt*8 + tq*2;
            float2 v1 = { acc[mt][nt][0] + bi1, acc[mt][nt][1] + bi1 };
            float2 v2 = { acc[mt][nt][2] + bi2, acc[mt][nt][3] + bi2 };
            if (emode == 0) {
                v1.x = tf32f(v1.x); v1.y = tf32f(v1.y);
                v2.x = tf32f(v2.x); v2.y = tf32f(v2.y);
            } else if (emode == 1) {
                v1.x = __expf(v1.x); v1.y = __expf(v1.y);
                v2.x = __expf(v2.x); v2.y = __expf(v2.y);
            }
            *(float2*)&Cb[(size_t)m1*HW + n]     = v1;
            *(float2*)&Cb[(size_t)(m1+8)*HW + n] = v2;
        }
    }
}

// -------- 4) context partials: 8-way n-split, 2x2 register blocking --------
__global__ __launch_bounds__(256)
void k_context() {
    int h = blockIdx.x, b = blockIdx.y, s = blockIdx.z;
    const int tid = threadIdx.x;
    const int d0 = (tid >> 4) << 1;
    const int e0 = (tid & 15) << 1;
    __shared__ float ek[32][129];
    __shared__ float vt[32][129];
    const float* kbase = g_qkv + ((size_t)(b*OQ) + HID   + h*32)*HW;
    const float* vbase = g_qkv + ((size_t)(b*OQ) + 2*HID + h*32)*HW;
    float a00 = 0.f, a01 = 0.f, a10 = 0.f, a11 = 0.f, s0 = 0.f, s1 = 0.f;
    const int nlo = s * (HW/NSPL);
    for (int n0 = nlo; n0 < nlo + HW/NSPL; n0 += 128) {
        #pragma unroll
        for (int i = tid; i < 1024; i += 256) {
            int r = i >> 5, c4 = (i & 31) << 2;
            float4 kv = *(const float4*)&kbase[(size_t)r*HW + n0 + c4];
            float4 vv = *(const float4*)&vbase[(size_t)r*HW + n0 + c4];
            ek[r][c4] = kv.x; ek[r][c4+1] = kv.y; ek[r][c4+2] = kv.z; ek[r][c4+3] = kv.w;
            vt[r][c4] = vv.x; vt[r][c4+1] = vv.y; vt[r][c4+2] = vv.z; vt[r][c4+3] = vv.w;
        }
        __syncthreads();
        #pragma unroll 8
        for (int nn = 0; nn < 128; nn++) {
            float k0 = ek[d0][nn], k1 = ek[d0+1][nn];
            float v0 = vt[e0][nn], v1 = vt[e0+1][nn];
            a00 += k0*v0; a01 += k0*v1;
            a10 += k1*v0; a11 += k1*v1;
            s0 += k0; s1 += k1;
        }
        __syncthreads();
    }
    size_t base = ((size_t)(b*4 + h)*NSPL + s) * 32;
    g_ctxp[(base + d0  )*32 + e0  ] = a00;
    g_ctxp[(base + d0  )*32 + e0+1] = a01;
    g_ctxp[(base + d0+1)*32 + e0  ] = a10;
    g_ctxp[(base + d0+1)*32 + e0+1] = a11;
    if (e0 == 0) { g_ctxs[base + d0] = s0; g_ctxs[base + d0+1] = s1; }
}

// -------- 5) reduce partials + fold out_w -> fragment-major tf32 g_M, per (b,h) --------
// g_M layout per batch: [ot(2)][ch(4)][wm(2)][mt(4)][ks(4)][lane(32)][4]
__global__ void k_fold(const float* __restrict__ out_w) {
    int b = blockIdx.x, h = blockIdx.y;
    const int tid = threadIdx.x;
    __shared__ float cs[1024];
    __shared__ float den[32];
    const size_t pbase = (size_t)(b*4 + h)*NSPL;
    for (int i = tid; i < 1024; i += 256) {
        float t = 0.f;
        #pragma unroll
        for (int sp = 0; sp < NSPL; sp++) t += g_ctxp[(pbase + sp)*1024 + i];
        cs[i] = t;
    }
    if (tid < 32) {
        float t = 0.f;
        #pragma unroll
        for (int sp = 0; sp < NSPL; sp++) t += g_ctxs[(pbase + sp)*32 + tid];
        den[tid] = 1.0f / t;
    }
    __syncthreads();
    int o = tid;
    // o-dependent fragment coords
    const int ot = o >> 7, o128 = o & 127;
    const int wm = o128 >> 6, mt = (o128 >> 4) & 3, gr = o128 & 15;
    const int gq = gr & 7, jr = gr >> 3;        // jr: row+8 bit
    const float* w = out_w + (size_t)o*HID + h*32;
    float wr[32];
    #pragma unroll
    for (int e = 0; e < 32; e++) wr[e] = w[e];
    float* Mb = g_M + (size_t)b*CCH*HID;
    for (int dd = 0; dd < 32; dd++) {
        int d = h*32 + dd;
        float acc = 0.f;
        #pragma unroll
        for (int e = 0; e < 32; e++) acc += wr[e] * cs[dd*32 + e];
        float val = tf32f(acc * den[dd]);
        // d-dependent fragment coords
        int ch = d >> 5, d32 = d & 31;
        int ks = d32 >> 3, r8 = d32 & 7;
        int tq = r8 & 3, jc = (r8 >> 2) & 1;    // jc: col+4 bit
        int j = jr + 2*jc;
        int lane = 4*gq + tq;
        size_t f4 = ((((((size_t)ot*4 + ch)*2 + wm)*4 + mt)*4 + ks)*32) + lane;
        Mb[f4*4 + j] = val;
    }
}

extern "C" void kernel_launch(void* const* d_in, const int* in_sizes, int n_in,
                              void* d_out, int out_size) {
    const float* x     = (const float*)d_in[0];
    const float* gn_w  = (const float*)d_in[1];
    const float* gn_b  = (const float*)d_in[2];
    const float* qkv_w = (const float*)d_in[3];
    const float* qkv_b = (const float*)d_in[4];
    const float* out_w = (const float*)d_in[5];
    const float* out_b = (const float*)d_in[6];
    float* out = (float*)d_out;

    float *p_wA, *p_qkv, *p_M, *p_bq;
    cudaGetSymbolAddress((void**)&p_wA,  g_wA);
    cudaGetSymbolAddress((void**)&p_qkv, g_qkv);
    cudaGetSymbolAddress((void**)&p_M,   g_M);
    cudaGetSymbolAddress((void**)&p_bq,  g_bq);

    cudaFuncSetAttribute((const void*)k_mma_gemm<1>, cudaFuncAttributeMaxDynamicSharedMemorySize, GSMEM);
    cudaFuncSetAttribute((const void*)k_mma_gemm<0>, cudaFuncAttributeMaxDynamicSharedMemorySize, GSMEM);

    // 1) GroupNorm stats
    k_gnstats<<<dim3(NGRP, BATCH), 256>>>(x, gn_w, gn_b);
    // 2) bias fold + weight prep (fragment-major)
    k_biasfold<<<dim3(BATCH, 3), 256>>>(qkv_w, qkv_b);
    k_prepw<<<dim3(96, BATCH), 256>>>(qkv_w);
    // 3) QKV GEMM: 384x4096x256 x16
    k_mma_gemm<1><<<dim3(HW/128, OQ/128, BATCH), 256, GSMEM>>>(
        p_wA, x, (long)CCH*HW, p_qkv, (long)OQ*HW,
        p_bq, (long)OQ, CCH);
    // 4) context partials
    k_context<<<dim3(4, BATCH, NSPL), 256>>>();
    // 5) reduce + fold out_w (fragment-major g_M)
    k_fold<<<dim3(BATCH, 4), 256>>>(out_w);
    // 6) output GEMM: 256x4096x128 x16
    k_mma_gemm<0><<<dim3(HW/128, CCH/128, BATCH), 256, GSMEM>>>(
        p_M, p_qkv, (long)OQ*HW, out, (long)CCH*HW,
        out_b, 0L, HID);
}

// round 15
// speedup vs baseline: 4.1897x; 1.2698x over previous
#include <cuda_runtime.h>
#include <cuda_fp16.h>
#include <math.h>
#include <stdint.h>

#define BATCH 16
#define CCH   256
#define HW    4096
#define OQ    384
#define HID   128
#define NGRP  32
#define CPG   8
#define EPS   1e-5f
#define NSPL  8

// -------- scratch --------
__device__ float  g_scale[BATCH*CCH];
__device__ float  g_shift[BATCH*CCH];
__device__ __half g_wAh[3*4*8192];                 // W fp16 fragment-major [tile3][ch4][ks4|wm2|mt4|lane32|8]
__device__ __half g_xh[(size_t)BATCH*HW*CCH];      // [b][n][cperm] fp16 (affine applied)
__device__ __half g_qh[(size_t)BATCH*HW*HID];      // [b][n][dperm] fp16
__device__ float  g_kv[(size_t)BATCH*2*HID*HW];    // rows 0..127 exp(k), 128..255 v
__device__ __half g_Mh[BATCH*2*2*8192];            // M fp16 fragment-major [b][tile2][ch2][...]
__device__ float  g_ctxp[BATCH*4*NSPL*32*32];
__device__ float  g_ctxs[BATCH*4*NSPL*32];

__device__ __forceinline__ uint32_t smem_u32(const void* p) {
    uint32_t a;
    asm("{ .reg .u64 t; cvta.to.shared.u64 t, %1; cvt.u32.u64 %0, t; }" : "=r"(a) : "l"(p));
    return a;
}
__device__ __forceinline__ void cp16(uint32_t saddr, const void* gptr) {
    asm volatile("cp.async.cg.shared.global [%0], [%1], 16;" :: "r"(saddr), "l"(gptr));
}
#define CP_COMMIT() asm volatile("cp.async.commit_group;" ::: "memory")
#define CP_WAIT0()  asm volatile("cp.async.wait_group 0;" ::: "memory")

// permuted position of k-index within its 16-block: (2t,2t+1,2t+8,2t+9) -> 4t..4t+3
__device__ __host__ __forceinline__ int dpos(int d) {
    int kk = d >> 4, r = d & 15;
    return kk*16 + ((r & 7) >> 1)*4 + ((r >> 3) << 1) + (r & 1);
}

// -------- 1) GroupNorm stats --------
__global__ void k_gnstats(const float* __restrict__ x,
                          const float* __restrict__ gn_w,
                          const float* __restrict__ gn_b) {
    int g = blockIdx.x, b = blockIdx.y;
    const float4* p4 = (const float4*)(x + ((size_t)b*CCH + g*CPG)*HW);
    const int n4 = CPG*HW/4;
    float s = 0.f, s2 = 0.f;
    for (int i = threadIdx.x; i < n4; i += blockDim.x) {
        float4 v = p4[i];
        s  += v.x + v.y + v.z + v.w;
        s2 += v.x*v.x + v.y*v.y + v.z*v.z + v.w*v.w;
    }
    __shared__ float ss[256], ss2[256];
    ss[threadIdx.x] = s; ss2[threadIdx.x] = s2;
    __syncthreads();
    for (int o = 128; o > 0; o >>= 1) {
        if (threadIdx.x < o) { ss[threadIdx.x] += ss[threadIdx.x+o]; ss2[threadIdx.x] += ss2[threadIdx.x+o]; }
        __syncthreads();
    }
    if (threadIdx.x < CPG) {
        const float inv = 1.0f / (float)(CPG*HW);
        float mean = ss[0] * inv;
        float var  = ss2[0] * inv - mean*mean;
        float r    = rsqrtf(var + EPS);
        int c = g*CPG + threadIdx.x;
        float a = gn_w[c] * r;
        g_scale[b*CCH + c] = a;
        g_shift[b*CCH + c] = gn_b[c] - mean*a;
    }
}

// -------- 2) transpose + affine + fp16 + k-perm: x[b,c,n] -> xh[b,n,cperm] --------
__global__ __launch_bounds__(256) void k_xt(const float* __restrict__ x) {
    __shared__ float ts[64][65];
    int b = blockIdx.z, c0 = blockIdx.y*64, n0 = blockIdx.x*64;
    int tid = threadIdx.x;
    const float* xb = x + ((size_t)b*CCH + c0)*HW + n0;
    #pragma unroll
    for (int t = 0; t < 4; t++) {
        int i = tid + t*256;
        int cc = i >> 4, n4 = (i & 15) << 2;
        float a = g_scale[b*CCH + c0 + cc], sh = g_shift[b*CCH + c0 + cc];
        float4 v = *(const float4*)&xb[(size_t)cc*HW + n4];
        ts[cc][n4]   = a*v.x + sh;
        ts[cc][n4+1] = a*v.y + sh;
        ts[cc][n4+2] = a*v.z + sh;
        ts[cc][n4+3] = a*v.w + sh;
    }
    __syncthreads();
    __half* ob = g_xh + ((size_t)b*HW + n0)*CCH + c0;
    #pragma unroll
    for (int t = 0; t < 8; t++) {
        int i = tid + t*256;
        int nn = i >> 5, p2 = i & 31;
        int blk = p2 >> 3, q = p2 & 7;
        int csrc = blk*16 + 2*(q >> 1) + 8*(q & 1);
        int pos  = blk*16 + 2*q;
        __half2 hv = __floats2half2_rn(ts[csrc][nn], ts[csrc+1][nn]);
        *(__half2*)&ob[(size_t)nn*CCH + pos] = hv;
    }
}

// -------- 3) prep W fp16 fragment-major (batch-independent) --------
__global__ void k_prepw(const float* __restrict__ qkv_w) {
    int f = blockIdx.x*256 + threadIdx.x;   // 0..12287
    int lane = f & 31;
    int u = f >> 5;
    int mt = u & 3, wm = (u >> 2) & 1, ks = (u >> 3) & 3, ch = (u >> 5) & 3, tile = u >> 7;
    int g = lane >> 2, t = lane & 3;
    int o = tile*128 + wm*64 + mt*16 + g;
    int k0 = (ch*4 + ks)*16 + 2*t;
    const float* w0 = qkv_w + (size_t)o*CCH;
    const float* w8 = qkv_w + (size_t)(o+8)*CCH;
    __half h[8];
    h[0] = __float2half_rn(w0[k0]);   h[1] = __float2half_rn(w0[k0+1]);
    h[2] = __float2half_rn(w8[k0]);   h[3] = __float2half_rn(w8[k0+1]);
    h[4] = __float2half_rn(w0[k0+8]); h[5] = __float2half_rn(w0[k0+9]);
    h[6] = __float2half_rn(w8[k0+8]); h[7] = __float2half_rn(w8[k0+9]);
    *(uint4*)&g_wAh[(size_t)f*8] = *(uint4*)h;
}

// -------- fp16 mma.sync GEMM, cp.async double-buffered, BK=64 --------
// CTA 128x128, 8 warps (2x4), warp tile 64x32 = 4x4 m16n8k16 per ks, 4 ks per chunk.
// A: fp16 fragment-major in gmem. B: fp16 [n][kperm] rows (browB bytes/row).
#define SZA (128*64*2)
#define SZB (128*64*2)
#define GSMEM (2*SZA + 2*SZB)
template<int MODE>   // 1 = QKV GEMM (3-way epilogue), 0 = output GEMM
__global__ __launch_bounds__(256, 2)
void k_mma_gemm(const __half* __restrict__ A, long strideAb, int tileStride,
                const __half* __restrict__ Bm, long strideBb, int browB,
                float* __restrict__ Cm, long strideC,
                const float* __restrict__ bias,
                __half* __restrict__ Qh, int K) {
    extern __shared__ char dsm[];
    const uint32_t sb = smem_u32(dsm);
    const int b = blockIdx.z;
    const int NCH = K >> 6;
    const __half* Afrag = A + (size_t)b*strideAb + (size_t)blockIdx.y*tileStride;
    const __half* Bb = Bm + (size_t)b*strideBb;
    float* Cb = Cm + (size_t)b*strideC;

    const int n0 = blockIdx.x * 128;
    const int tid = threadIdx.x;
    const int lane = tid & 31, warp = tid >> 5;
    const int warpM = warp >> 2, warpN = warp & 3;
    const int gq = lane >> 2, tq = lane & 3;

    float acc[4][4][4];
    #pragma unroll
    for (int i = 0; i < 4; i++)
    #pragma unroll
    for (int j = 0; j < 4; j++)
    #pragma unroll
    for (int r = 0; r < 4; r++) acc[i][j][r] = 0.f;

    auto load_chunk = [&](int ch, int st) {
        const uint32_t aBase = sb + st*SZA;
        const uint32_t bBase = sb + 2*SZA + st*SZB;
        const __half* Asrc = Afrag + (size_t)ch*8192;
        #pragma unroll
        for (int t = 0; t < 4; t++) {
            int i = tid + t*256;
            cp16(aBase + (uint32_t)i*16, Asrc + i*8);
        }
        #pragma unroll
        for (int t = 0; t < 4; t++) {
            int i = tid + t*256;
            int n = i >> 3, ks = (i >> 1) & 3, h = i & 1;
            cp16(bBase + (uint32_t)(ks*4096 + n*32 + h*16),
                 (const char*)Bb + (size_t)(n0+n)*browB + ch*128 + ks*32 + h*16);
        }
        CP_COMMIT();
    };

    load_chunk(0, 0);

    for (int ch = 0; ch < NCH; ch++) {
        CP_WAIT0();
        __syncthreads();
        if (ch + 1 < NCH) load_chunk(ch+1, (ch+1)&1);

        const char* aSt = dsm + (ch&1)*SZA;
        const char* bSt = dsm + 2*SZA + (ch&1)*SZB;

        #pragma unroll
        for (int ks = 0; ks < 4; ks++) {
            uint4 af[4];
            #pragma unroll
            for (int mt = 0; mt < 4; mt++)
                af[mt] = *(const uint4*)(aSt + (size_t)(((ks*2 + warpM)*4 + mt)*32 + lane)*16);
            uint2 bf[4];
            #pragma unroll
            for (int nt = 0; nt < 4; nt++)
                bf[nt] = *(const uint2*)(bSt + (size_t)(ks*4096 + (warpN*32 + nt*8 + gq)*32 + tq*8));
            #pragma unroll
            for (int mt = 0; mt < 4; mt++)
            #pragma unroll
            for (int nt = 0; nt < 4; nt++) {
                asm volatile(
                    "mma.sync.aligned.m16n8k16.row.col.f32.f16.f16.f32 "
                    "{%0,%1,%2,%3}, {%4,%5,%6,%7}, {%8,%9}, {%0,%1,%2,%3};"
                    : "+f"(acc[mt][nt][0]), "+f"(acc[mt][nt][1]),
                      "+f"(acc[mt][nt][2]), "+f"(acc[mt][nt][3])
                    : "r"(af[mt].x), "r"(af[mt].y), "r"(af[mt].z), "r"(af[mt].w),
                      "r"(bf[nt].x), "r"(bf[nt].y));
            }
        }
    }

    __syncthreads();
    if (MODE == 1 && blockIdx.y == 0) {
        // q rows -> fp16 [n][dperm]
        #pragma unroll
        for (int mt = 0; mt < 4; mt++) {
            int d1 = warpM*64 + mt*16 + gq;
            float bi1 = bias[d1], bi2 = bias[d1+8];
            int p1 = dpos(d1), p2 = dpos(d1+8);
            #pragma unroll
            for (int nt = 0; nt < 4; nt++) {
                int n = n0 + warpN*32 + nt*8 + tq*2;
                __half* q0 = &Qh[((size_t)b*HW + n)*HID];
                q0[p1]       = __float2half_rn(acc[mt][nt][0] + bi1);
                q0[HID + p1] = __float2half_rn(acc[mt][nt][1] + bi1);
                q0[p2]       = __float2half_rn(acc[mt][nt][2] + bi2);
                q0[HID + p2] = __float2half_rn(acc[mt][nt][3] + bi2);
            }
        }
    } else {
        const int rbase = (MODE == 1) ? ((int)blockIdx.y - 1)*128 : (int)blockIdx.y*128;
        const bool ex = (MODE == 1) && (blockIdx.y == 1);
        #pragma unroll
        for (int mt = 0; mt < 4; mt++) {
            int loc = warpM*64 + mt*16 + gq;
            int ob = (int)blockIdx.y*128 + loc;
            float bi1 = bias[ob], bi2 = bias[ob+8];
            int r1 = rbase + loc;
            #pragma unroll
            for (int nt = 0; nt < 4; nt++) {
                int n = n0 + warpN*32 + nt*8 + tq*2;
                float2 v1 = { acc[mt][nt][0] + bi1, acc[mt][nt][1] + bi1 };
                float2 v2 = { acc[mt][nt][2] + bi2, acc[mt][nt][3] + bi2 };
                if (ex) {
                    v1.x = __expf(v1.x); v1.y = __expf(v1.y);
                    v2.x = __expf(v2.x); v2.y = __expf(v2.y);
                }
                *(float2*)&Cb[(size_t)r1*HW + n]     = v1;
                *(float2*)&Cb[(size_t)(r1+8)*HW + n] = v2;
            }
        }
    }
}

// -------- 4) context partials: 8-way n-split, 2x2 register blocking --------
__global__ __launch_bounds__(256)
void k_context() {
    int h = blockIdx.x, b = blockIdx.y, s = blockIdx.z;
    const int tid = threadIdx.x;
    const int d0 = (tid >> 4) << 1;
    const int e0 = (tid & 15) << 1;
    __shared__ float ek[32][129];
    __shared__ float vt[32][129];
    const float* kbase = g_kv + ((size_t)b*2*HID + h*32)*HW;
    const float* vbase = g_kv + ((size_t)b*2*HID + HID + h*32)*HW;
    float a00 = 0.f, a01 = 0.f, a10 = 0.f, a11 = 0.f, s0 = 0.f, s1 = 0.f;
    const int nlo = s * (HW/NSPL);
    for (int n0 = nlo; n0 < nlo + HW/NSPL; n0 += 128) {
        #pragma unroll
        for (int i = tid; i < 1024; i += 256) {
            int r = i >> 5, c4 = (i & 31) << 2;
            float4 kv = *(const float4*)&kbase[(size_t)r*HW + n0 + c4];
            float4 vv = *(const float4*)&vbase[(size_t)r*HW + n0 + c4];
            ek[r][c4] = kv.x; ek[r][c4+1] = kv.y; ek[r][c4+2] = kv.z; ek[r][c4+3] = kv.w;
            vt[r][c4] = vv.x; vt[r][c4+1] = vv.y; vt[r][c4+2] = vv.z; vt[r][c4+3] = vv.w;
        }
        __syncthreads();
        #pragma unroll 8
        for (int nn = 0; nn < 128; nn++) {
            float k0 = ek[d0][nn], k1 = ek[d0+1][nn];
            float v0 = vt[e0][nn], v1 = vt[e0+1][nn];
            a00 += k0*v0; a01 += k0*v1;
            a10 += k1*v0; a11 += k1*v1;
            s0 += k0; s1 += k1;
        }
        __syncthreads();
    }
    size_t base = ((size_t)(b*4 + h)*NSPL + s) * 32;
    g_ctxp[(base + d0  )*32 + e0  ] = a00;
    g_ctxp[(base + d0  )*32 + e0+1] = a01;
    g_ctxp[(base + d0+1)*32 + e0  ] = a10;
    g_ctxp[(base + d0+1)*32 + e0+1] = a11;
    if (e0 == 0) { g_ctxs[base + d0] = s0; g_ctxs[base + d0+1] = s1; }
}

// -------- 5) reduce partials + fold out_w -> fp16 fragment-major g_Mh --------
__global__ void k_fold(const float* __restrict__ out_w) {
    int b = blockIdx.x, h = blockIdx.y;
    const int tid = threadIdx.x;
    __shared__ float cs[1024];
    __shared__ float den[32];
    const size_t pbase = (size_t)(b*4 + h)*NSPL;
    for (int i = tid; i < 1024; i += 256) {
        float t = 0.f;
        #pragma unroll
        for (int sp = 0; sp < NSPL; sp++) t += g_ctxp[(pbase + sp)*1024 + i];
        cs[i] = t;
    }
    if (tid < 32) {
        float t = 0.f;
        #pragma unroll
        for (int sp = 0; sp < NSPL; sp++) t += g_ctxs[(pbase + sp)*32 + tid];
        den[tid] = 1.0f / t;
    }
    __syncthreads();
    int o = tid;
    const int tile = o >> 7, o128 = o & 127;
    const int wm = o128 >> 6, mt = (o128 >> 4) & 3, gr = o128 & 15;
    const int g = gr & 7, rowhi = gr >> 3;
    const float* w = out_w + (size_t)o*HID + h*32;
    float wr[32];
    #pragma unroll
    for (int e = 0; e < 32; e++) wr[e] = w[e];
    __half* Mb = g_Mh + (size_t)b*32768;
    for (int dd = 0; dd < 32; dd++) {
        int d = h*32 + dd;
        float acc = 0.f;
        #pragma unroll
        for (int e = 0; e < 32; e++) acc += wr[e] * cs[dd*32 + e];
        float val = acc * den[dd];
        int kk = d >> 4, r = d & 15;
        int ks = kk & 3, ch = kk >> 2;
        int t = (r & 7) >> 1, jlow = r & 1, colhi = (r >> 3) & 1;
        int lane = g*4 + t;
        int sub = colhi*4 + rowhi*2 + jlow;
        size_t idx = (size_t)tile*16384 + (size_t)ch*8192
                   + (size_t)(((ks*2 + wm)*4 + mt)*32 + lane)*8 + sub;
        Mb[idx] = __float2half_rn(val);
    }
}

extern "C" void kernel_launch(void* const* d_in, const int* in_sizes, int n_in,
                              void* d_out, int out_size) {
    const float* x     = (const float*)d_in[0];
    const float* gn_w  = (const float*)d_in[1];
    const float* gn_b  = (const float*)d_in[2];
    const float* qkv_w = (const float*)d_in[3];
    const float* qkv_b = (const float*)d_in[4];
    const float* out_w = (const float*)d_in[5];
    const float* out_b = (const float*)d_in[6];
    float* out = (float*)d_out;

    __half *p_wAh, *p_xh, *p_qh, *p_Mh;
    float *p_kv;
    cudaGetSymbolAddress((void**)&p_wAh, g_wAh);
    cudaGetSymbolAddress((void**)&p_xh,  g_xh);
    cudaGetSymbolAddress((void**)&p_qh,  g_qh);
    cudaGetSymbolAddress((void**)&p_Mh,  g_Mh);
    cudaGetSymbolAddress((void**)&p_kv,  g_kv);

    cudaFuncSetAttribute((const void*)k_mma_gemm<1>, cudaFuncAttributeMaxDynamicSharedMemorySize, GSMEM);
    cudaFuncSetAttribute((const void*)k_mma_gemm<0>, cudaFuncAttributeMaxDynamicSharedMemorySize, GSMEM);

    // 1) GroupNorm stats
    k_gnstats<<<dim3(NGRP, BATCH), 256>>>(x, gn_w, gn_b);
    // 2) x -> fp16 transposed+affine+perm
    k_xt<<<dim3(HW/64, CCH/64, BATCH), 256>>>(x);
    // 3) W -> fp16 fragment-major (batch-independent)
    k_prepw<<<48, 256>>>(qkv_w);
    // 4) QKV GEMM fp16: 384x4096x256 x16
    k_mma_gemm<1><<<dim3(HW/128, 3, BATCH), 256, GSMEM>>>(
        p_wAh, 0L, 32768, p_xh, (long)HW*CCH, 512,
        p_kv, (long)2*HID*HW, qkv_b, p_qh, CCH);
    // 5) context partials
    k_context<<<dim3(4, BATCH, NSPL), 256>>>();
    // 6) reduce + fold -> fp16 fragment-major M
    k_fold<<<dim3(BATCH, 4), 256>>>(out_w);
    // 7) output GEMM fp16: 256x4096x128 x16
    k_mma_gemm<0><<<dim3(HW/128, 2, BATCH), 256, GSMEM>>>(
        p_Mh, 32768L, 16384, p_qh, (long)HW*HID, 256,
        out, (long)CCH*HW, out_b, nullptr, HID);
}